// round 7
// baseline (speedup 1.0000x reference)
#include <cuda_runtime.h>
#include <cuda_bf16.h>
#include <math.h>
#include <cstdint>

#define Bn   8
#define Cn   64
#define Hn   128
#define Wn   128
#define PIX  (Bn*Hn*Wn)    // 131072

// offmask smem (bytes): aH 66560 | aL 66560 | wH 36864 | wL 36864
#define O_AL 66560
#define O_WH 133120
#define O_WL 169984
#define OSM  206848
// deform smem: aH 32768 | aL 32768 | wH 8192 | wL 8192 | psm 8192
#define D_AL 32768
#define D_WH 65536
#define D_WL 73728
#define D_PS 81920
#define DSM  90112

// Scratch
__device__ float g_xt[PIX*Cn];            // x channels-last
__device__ float g_om[PIX*27];            // offsets+mask per pixel
__device__ float g_y [PIX*Cn];            // deform out [pix][c]
__device__ __nv_bfloat16 g_wdh[9*64*64];  // deform W hi   [tap][o][c]
__device__ __nv_bfloat16 g_wdl[9*64*64];  // deform W lo
__device__ __nv_bfloat16 g_woh[9*32*64];  // offmask W hi  [tap][o(32)][c]
__device__ __nv_bfloat16 g_wol[9*32*64];  // offmask W lo
__device__ float g_sum[Cn];
__device__ float g_sq [Cn];

#define MMA16816(d0,d1,d2,d3,a0,a1,a2,a3,b0,b1) \
    asm volatile("mma.sync.aligned.m16n8k16.row.col.f32.bf16.bf16.f32 " \
        "{%0,%1,%2,%3}, {%4,%5,%6,%7}, {%8,%9}, {%0,%1,%2,%3};" \
        : "+f"(d0), "+f"(d1), "+f"(d2), "+f"(d3) \
        : "r"(a0), "r"(a1), "r"(a2), "r"(a3), "r"(b0), "r"(b1))

#define LDSM4(r0,r1,r2,r3,a) \
    asm volatile("ldmatrix.sync.aligned.m8n8.x4.shared.b16 {%0,%1,%2,%3}, [%4];" \
        : "=r"(r0), "=r"(r1), "=r"(r2), "=r"(r3) : "r"(a))

__device__ __forceinline__ uint32_t lds_addr(const void* p) {
    return (uint32_t)__cvta_generic_to_shared(p);
}
__device__ __forceinline__ uint32_t pkbf(__nv_bfloat16 a, __nv_bfloat16 b) {
    uint32_t r;
    asm("mov.b32 %0, {%1, %2};" : "=r"(r)
        : "h"(__bfloat16_as_ushort(a)), "h"(__bfloat16_as_ushort(b)));
    return r;
}
__device__ __forceinline__ void split4(float4 v, uint2& hi, uint2& lo) {
    __nv_bfloat16 hx = __float2bfloat16_rn(v.x), hy = __float2bfloat16_rn(v.y);
    __nv_bfloat16 hz = __float2bfloat16_rn(v.z), hw = __float2bfloat16_rn(v.w);
    hi.x = pkbf(hx, hy); hi.y = pkbf(hz, hw);
    __nv_bfloat16 lx = __float2bfloat16_rn(v.x - __bfloat162float(hx));
    __nv_bfloat16 ly = __float2bfloat16_rn(v.y - __bfloat162float(hy));
    __nv_bfloat16 lz = __float2bfloat16_rn(v.z - __bfloat162float(hz));
    __nv_bfloat16 lw = __float2bfloat16_rn(v.w - __bfloat162float(hw));
    lo.x = pkbf(lx, ly); lo.y = pkbf(lz, lw);
}

// ---------------------------------------------------------------------------
__global__ void k_zero() {
    int i = threadIdx.x;
    if (i < Cn) { g_sum[i] = 0.f; g_sq[i] = 0.f; }
}

// ---------------------------------------------------------------------------
__global__ __launch_bounds__(256) void k_wprep(
    const float* __restrict__ wmat,
    const float* __restrict__ off_w, const float* __restrict__ mod_w)
{
    for (int i = blockIdx.x*256 + threadIdx.x; i < 9*4096 + 9*2048; i += gridDim.x*256) {
        if (i < 9*4096) {
            int tap = i >> 12, r = i & 4095;
            int o = r >> 6, c = r & 63;
            float v = wmat[(o*64 + c)*9 + tap];
            __nv_bfloat16 h = __float2bfloat16_rn(v);
            __nv_bfloat16 l = __float2bfloat16_rn(v - __bfloat162float(h));
            g_wdh[i] = h; g_wdl[i] = l;
        } else {
            int j = i - 9*4096;
            int tap = j >> 11, r = j & 2047;
            int o = r >> 6, c = r & 63;
            float v = 0.f;
            if (o < 18)      v = off_w[(o*64 + c)*9 + tap];
            else if (o < 27) v = mod_w[((o-18)*64 + c)*9 + tap];
            __nv_bfloat16 h = __float2bfloat16_rn(v);
            __nv_bfloat16 l = __float2bfloat16_rn(v - __bfloat162float(h));
            g_woh[j] = h; g_wol[j] = l;
        }
    }
}

// ---------------------------------------------------------------------------
__global__ __launch_bounds__(1024) void k_transpose_in(const float* __restrict__ x) {
    __shared__ float t[32][33];
    int w0 = blockIdx.x * 32, c0 = blockIdx.y * 32;
    int bh = blockIdx.z;
    int b = bh / Hn, h = bh % Hn;
    int tx = threadIdx.x, ty = threadIdx.y;
    t[ty][tx] = x[(((b*Cn) + (c0+ty))*Hn + h)*Wn + (w0+tx)];
    __syncthreads();
    g_xt[((size_t)bh*Wn + (w0+ty))*Cn + (c0+tx)] = t[tx][ty];
}

// ---------------------------------------------------------------------------
// offset/mask conv: 512 thr, 2 output rows (256 px). Halo A (4x130 rows) and
// ALL 9 taps' W staged once; single sync; pure LDSM+HMMA stream after.
__global__ __launch_bounds__(512) void k_offmask(
    const float* __restrict__ off_b, const float* __restrict__ mod_b)
{
    extern __shared__ __align__(16) char sm[];
    char* aH = sm;          char* aL = sm + O_AL;
    char* wH = sm + O_WH;   char* wL = sm + O_WL;
    uint32_t aHb = lds_addr(aH), aLb = lds_addr(aL);
    uint32_t wHb = lds_addr(wH), wLb = lds_addr(wL);

    int tid = threadIdx.x;
    int wid = tid >> 5, lane = tid & 31;
    int g = lane >> 2, tc = lane & 3;
    int lrow = lane & 7, lmat = lane >> 3;
    int blk = blockIdx.x;
    int b = blk >> 6, h0 = (blk & 63) * 2;

    // stage W: all 9 taps, 288 rows x 128B each of hi/lo, swizzled
    for (int i = tid; i < 2304; i += 512) {
        int row = i >> 3, q = i & 7;
        int off = row*128 + ((q*16) ^ ((row & 7)*16));
        *(uint4*)(wH + off) = ((const uint4*)g_woh)[i];
        *(uint4*)(wL + off) = ((const uint4*)g_wol)[i];
    }
    // stage A halo: 4 rows x 130 px, bf16 hi/lo, swizzled
    for (int i = tid; i < 520*16; i += 512) {
        int rc = i >> 4, c4 = i & 15;
        int r4 = rc / 130, hx = rc - r4*130;
        int y = h0 + r4 - 1, xx = hx - 1;
        float4 v = make_float4(0.f,0.f,0.f,0.f);
        if (y >= 0 && y < Hn && xx >= 0 && xx < Wn)
            v = *(const float4*)&g_xt[(((size_t)b*Hn + y)*Wn + xx)*Cn + c4*4];
        uint2 hi, lo; split4(v, hi, lo);
        int off = rc*128 + ((c4*8) ^ ((rc & 7)*16));
        *(uint2*)(aH + off) = hi;
        *(uint2*)(aL + off) = lo;
    }
    __syncthreads();

    float dacc[4][4];
    #pragma unroll
    for (int n = 0; n < 4; n++)
        #pragma unroll
        for (int q = 0; q < 4; q++) dacc[n][q] = 0.f;

    int r = wid >> 3;                 // output row within block
    int w0 = (wid & 7) << 4;          // 16-px window
    int browb = ((lmat >> 1) << 3) + lrow;
    int bsw  = (browb & 7) << 4;
    int bcol = (lmat & 1) << 4;
    int acol = (lmat >> 1) << 4;
    int asub = ((lmat & 1) << 3) + lrow;

    for (int tap = 0; tap < 9; tap++) {
        int ky = tap/3, kx = tap - ky*3;
        int arow = (r + ky)*130 + kx + w0 + asub;
        uint32_t aRowOff = arow*128;
        int asw = (arow & 7) << 4;
        #pragma unroll
        for (int ks = 0; ks < 4; ks++) {
            uint32_t aoff = aRowOff + ((acol + ks*32) ^ asw);
            uint32_t ah0,ah1,ah2,ah3, al0,al1,al2,al3;
            LDSM4(ah0,ah1,ah2,ah3, aHb + aoff);
            LDSM4(al0,al1,al2,al3, aLb + aoff);
            #pragma unroll
            for (int np = 0; np < 2; np++) {
                int wrow = tap*32 + np*16 + browb;
                uint32_t boff = wrow*128 + ((bcol + ks*32) ^ bsw);
                uint32_t bh0,bh1,bh2,bh3, bl0,bl1,bl2,bl3;
                LDSM4(bh0,bh1,bh2,bh3, wHb + boff);
                LDSM4(bl0,bl1,bl2,bl3, wLb + boff);
                MMA16816(dacc[2*np][0],dacc[2*np][1],dacc[2*np][2],dacc[2*np][3],
                         ah0,ah1,ah2,ah3, bh0,bh1);
                MMA16816(dacc[2*np][0],dacc[2*np][1],dacc[2*np][2],dacc[2*np][3],
                         al0,al1,al2,al3, bh0,bh1);
                MMA16816(dacc[2*np][0],dacc[2*np][1],dacc[2*np][2],dacc[2*np][3],
                         ah0,ah1,ah2,ah3, bl0,bl1);
                MMA16816(dacc[2*np+1][0],dacc[2*np+1][1],dacc[2*np+1][2],dacc[2*np+1][3],
                         ah0,ah1,ah2,ah3, bh2,bh3);
                MMA16816(dacc[2*np+1][0],dacc[2*np+1][1],dacc[2*np+1][2],dacc[2*np+1][3],
                         al0,al1,al2,al3, bh2,bh3);
                MMA16816(dacc[2*np+1][0],dacc[2*np+1][1],dacc[2*np+1][2],dacc[2*np+1][3],
                         ah0,ah1,ah2,ah3, bl2,bl3);
            }
        }
    }

    // epilogue
    int px = ((b*Hn) + h0 + r)*Wn + w0 + g;
    #pragma unroll
    for (int nt = 0; nt < 4; nt++) {
        int o = nt*8 + 2*tc;
        if (o < 27) {
            float v0 = dacc[nt][0], v2 = dacc[nt][2];
            if (o < 18) { v0 += off_b[o]; v2 += off_b[o]; }
            else {
                v0 = 2.0f / (1.0f + expf(-(v0 + mod_b[o-18])));
                v2 = 2.0f / (1.0f + expf(-(v2 + mod_b[o-18])));
            }
            g_om[(size_t)px*27 + o]     = v0;
            g_om[(size_t)(px+8)*27 + o] = v2;
        }
        if (o+1 < 27) {
            float v1 = dacc[nt][1], v3 = dacc[nt][3];
            if (o+1 < 18) { v1 += off_b[o+1]; v3 += off_b[o+1]; }
            else {
                v1 = 2.0f / (1.0f + expf(-(v1 + mod_b[o+1-18])));
                v3 = 2.0f / (1.0f + expf(-(v3 + mod_b[o+1-18])));
            }
            g_om[(size_t)px*27 + o+1]     = v1;
            g_om[(size_t)(px+8)*27 + o+1] = v3;
        }
    }
}

// ---------------------------------------------------------------------------
// Deformable conv: 256 thr, 256 px/block, warp = 32 px (2 m16 frags), N=64.
// Per tap: {params || W stage} -> gather+STS -> MMA. Fused BN stats.
__global__ __launch_bounds__(256) void k_deform(const float* __restrict__ bias)
{
    extern __shared__ __align__(16) char sm[];
    char* aH = sm;          char* aL = sm + D_AL;
    char* wH = sm + D_WH;   char* wL = sm + D_WL;
    float* psm = (float*)(sm + D_PS);
    uint32_t aHb = lds_addr(aH), aLb = lds_addr(aL);
    uint32_t wHb = lds_addr(wH), wLb = lds_addr(wL);

    int tid = threadIdx.x;
    int wid = tid >> 5, lane = tid & 31;
    int g = lane >> 2, tc = lane & 3;
    int lrow = lane & 7, lmat = lane >> 3;
    int blk = blockIdx.x;
    int b = blk >> 6, h0 = (blk & 63) * 2;
    int p0 = blk * 256;
    int c4 = tid & 15, grp = tid >> 4;

    float d0c[8][4], d1c[8][4];
    #pragma unroll
    for (int n = 0; n < 8; n++)
        #pragma unroll
        for (int q = 0; q < 4; q++) { d0c[n][q] = 0.f; d1c[n][q] = 0.f; }

    int arow = wid*32 + ((lmat & 1) << 3) + lrow;
    uint32_t aRowOff = arow*128;
    int asw  = (lrow) << 4;           // arow&7 == lrow (wid*32, 8-offsets are mult of 8)
    int acol = (lmat >> 1) << 4;
    int browb = ((lmat >> 1) << 3) + lrow;
    int bsw  = (browb & 7) << 4;
    int bcol = (lmat & 1) << 4;

    for (int tap = 0; tap < 9; tap++) {
        int ky = tap/3, kx = tap - ky*3;
        __syncthreads();
        // params (1 thread / pixel) + W stage, same phase
        {
            const float* omp = &g_om[(size_t)(p0 + tid)*27];
            float dy = omp[tap*2], dx = omp[tap*2+1], mk = omp[18+tap];
            int row = h0 + (tid >> 7), w = tid & 127;
            float py = (float)(row + ky - 1) + dy;
            float px_ = (float)(w + kx - 1) + dx;
            float fy = floorf(py), fx = floorf(px_);
            float ly = py - fy,    lx = px_ - fx;
            int y0 = (int)fy, x0 = (int)fx;
            int y1 = y0 + 1,  x1 = x0 + 1;
            float vy0 = (y0 >= 0 && y0 < Hn) ? 1.f : 0.f;
            float vy1 = (y1 >= 0 && y1 < Hn) ? 1.f : 0.f;
            float vx0 = (x0 >= 0 && x0 < Wn) ? 1.f : 0.f;
            float vx1 = (x1 >= 0 && x1 < Wn) ? 1.f : 0.f;
            int iy0 = min(max(y0,0),Hn-1), iy1 = min(max(y1,0),Hn-1);
            int ix0 = min(max(x0,0),Wn-1), ix1 = min(max(x1,0),Wn-1);
            int base = (b*Hn)*Wn;
            psm[tid*8+0] = (1.f-ly)*(1.f-lx)*mk * vy0*vx0;
            psm[tid*8+1] = (1.f-ly)*lx      *mk * vy0*vx1;
            psm[tid*8+2] = ly      *(1.f-lx)*mk * vy1*vx0;
            psm[tid*8+3] = ly      *lx      *mk * vy1*vx1;
            psm[tid*8+4] = __int_as_float(((base + iy0*Wn + ix0)*Cn) >> 2);
            psm[tid*8+5] = __int_as_float(((base + iy0*Wn + ix1)*Cn) >> 2);
            psm[tid*8+6] = __int_as_float(((base + iy1*Wn + ix0)*Cn) >> 2);
            psm[tid*8+7] = __int_as_float(((base + iy1*Wn + ix1)*Cn) >> 2);
        }
        for (int i = tid; i < 512; i += 256) {
            int row = i >> 3, q = i & 7;
            int off = row*128 + ((q*16) ^ ((row & 7)*16));
            *(uint4*)(wH + off) = ((const uint4*)&g_wdh[tap*4096])[i];
            *(uint4*)(wL + off) = ((const uint4*)&g_wdl[tap*4096])[i];
        }
        __syncthreads();
        // cooperative gather + blend + split (16 lanes/px, 16 groups)
        {
            const float4* P = (const float4*)g_xt;
            #pragma unroll 2
            for (int it = 0; it < 16; it++) {
                int px = it*16 + grp;
                float w00 = psm[px*8+0], w01 = psm[px*8+1];
                float w10 = psm[px*8+2], w11 = psm[px*8+3];
                int i00 = __float_as_int(psm[px*8+4]);
                int i01 = __float_as_int(psm[px*8+5]);
                int i10 = __float_as_int(psm[px*8+6]);
                int i11 = __float_as_int(psm[px*8+7]);
                float4 a = P[i00 + c4], e = P[i01 + c4];
                float4 c = P[i10 + c4], d = P[i11 + c4];
                float4 v;
                v.x = w00*a.x + w01*e.x + w10*c.x + w11*d.x;
                v.y = w00*a.y + w01*e.y + w10*c.y + w11*d.y;
                v.z = w00*a.z + w01*e.z + w10*c.z + w11*d.z;
                v.w = w00*a.w + w01*e.w + w10*c.w + w11*d.w;
                uint2 hi, lo; split4(v, hi, lo);
                int off = px*128 + ((c4*8) ^ ((px & 7)*16));
                *(uint2*)(aH + off) = hi;
                *(uint2*)(aL + off) = lo;
            }
        }
        __syncthreads();
        #pragma unroll
        for (int ks = 0; ks < 4; ks++) {
            uint32_t aoff = aRowOff + ((acol + ks*32) ^ asw);
            uint32_t ah0,ah1,ah2,ah3, al0,al1,al2,al3;
            uint32_t ag0,ag1,ag2,ag3, am0,am1,am2,am3;
            LDSM4(ah0,ah1,ah2,ah3, aHb + aoff);
            LDSM4(al0,al1,al2,al3, aLb + aoff);
            LDSM4(ag0,ag1,ag2,ag3, aHb + aoff + 2048);   // m1 (+16 rows)
            LDSM4(am0,am1,am2,am3, aLb + aoff + 2048);
            #pragma unroll
            for (int np = 0; np < 4; np++) {
                uint32_t boff = (np*16 + browb)*128 + ((bcol + ks*32) ^ bsw);
                uint32_t bh0,bh1,bh2,bh3, bl0,bl1,bl2,bl3;
                LDSM4(bh0,bh1,bh2,bh3, wHb + boff);
                LDSM4(bl0,bl1,bl2,bl3, wLb + boff);
                MMA16816(d0c[2*np][0],d0c[2*np][1],d0c[2*np][2],d0c[2*np][3],
                         ah0,ah1,ah2,ah3, bh0,bh1);
                MMA16816(d0c[2*np][0],d0c[2*np][1],d0c[2*np][2],d0c[2*np][3],
                         al0,al1,al2,al3, bh0,bh1);
                MMA16816(d0c[2*np][0],d0c[2*np][1],d0c[2*np][2],d0c[2*np][3],
                         ah0,ah1,ah2,ah3, bl0,bl1);
                MMA16816(d0c[2*np+1][0],d0c[2*np+1][1],d0c[2*np+1][2],d0c[2*np+1][3],
                         ah0,ah1,ah2,ah3, bh2,bh3);
                MMA16816(d0c[2*np+1][0],d0c[2*np+1][1],d0c[2*np+1][2],d0c[2*np+1][3],
                         al0,al1,al2,al3, bh2,bh3);
                MMA16816(d0c[2*np+1][0],d0c[2*np+1][1],d0c[2*np+1][2],d0c[2*np+1][3],
                         ah0,ah1,ah2,ah3, bl2,bl3);
                MMA16816(d1c[2*np][0],d1c[2*np][1],d1c[2*np][2],d1c[2*np][3],
                         ag0,ag1,ag2,ag3, bh0,bh1);
                MMA16816(d1c[2*np][0],d1c[2*np][1],d1c[2*np][2],d1c[2*np][3],
                         am0,am1,am2,am3, bh0,bh1);
                MMA16816(d1c[2*np][0],d1c[2*np][1],d1c[2*np][2],d1c[2*np][3],
                         ag0,ag1,ag2,ag3, bl0,bl1);
                MMA16816(d1c[2*np+1][0],d1c[2*np+1][1],d1c[2*np+1][2],d1c[2*np+1][3],
                         ag0,ag1,ag2,ag3, bh2,bh3);
                MMA16816(d1c[2*np+1][0],d1c[2*np+1][1],d1c[2*np+1][2],d1c[2*np+1][3],
                         am0,am1,am2,am3, bh2,bh3);
                MMA16816(d1c[2*np+1][0],d1c[2*np+1][1],d1c[2*np+1][2],d1c[2*np+1][3],
                         ag0,ag1,ag2,ag3, bl2,bl3);
            }
        }
    }

    // epilogue: +bias, store y, fused BN stats
    __syncthreads();
    if (tid < 128) psm[tid] = 0.f;
    __syncthreads();

    float ss[8], sh[8], qs[8], qh[8];
    #pragma unroll
    for (int nt = 0; nt < 8; nt++) { ss[nt]=0.f; sh[nt]=0.f; qs[nt]=0.f; qh[nt]=0.f; }
    #pragma unroll
    for (int m = 0; m < 2; m++) {
        int px = p0 + wid*32 + m*16 + g;
        #pragma unroll
        for (int nt = 0; nt < 8; nt++) {
            float (*dc)[4] = m ? d1c : d0c;
            int o = nt*8 + 2*tc;
            float b0 = bias[o], b1 = bias[o+1];
            float v00 = dc[nt][0] + b0, v01 = dc[nt][1] + b1;
            float v10 = dc[nt][2] + b0, v11 = dc[nt][3] + b1;
            *(float2*)&g_y[(size_t)px*64 + o]     = make_float2(v00, v01);
            *(float2*)&g_y[(size_t)(px+8)*64 + o] = make_float2(v10, v11);
            ss[nt] += v00 + v10;         sh[nt] += v01 + v11;
            qs[nt] += v00*v00 + v10*v10; qh[nt] += v01*v01 + v11*v11;
        }
    }
    #pragma unroll
    for (int d = 4; d < 32; d <<= 1) {
        #pragma unroll
        for (int nt = 0; nt < 8; nt++) {
            ss[nt] += __shfl_xor_sync(0xffffffffu, ss[nt], d);
            sh[nt] += __shfl_xor_sync(0xffffffffu, sh[nt], d);
            qs[nt] += __shfl_xor_sync(0xffffffffu, qs[nt], d);
            qh[nt] += __shfl_xor_sync(0xffffffffu, qh[nt], d);
        }
    }
    if (lane < 4) {
        #pragma unroll
        for (int nt = 0; nt < 8; nt++) {
            int o = nt*8 + 2*tc;
            atomicAdd(&psm[o],       ss[nt]);
            atomicAdd(&psm[o+1],     sh[nt]);
            atomicAdd(&psm[64+o],    qs[nt]);
            atomicAdd(&psm[64+o+1],  qh[nt]);
        }
    }
    __syncthreads();
    if (tid < 64) {
        atomicAdd(&g_sum[tid], psm[tid]);
        atomicAdd(&g_sq [tid], psm[64+tid]);
    }
}

// ---------------------------------------------------------------------------
__global__ __launch_bounds__(1024) void k_norm_out(
    const float* __restrict__ gamma, const float* __restrict__ beta,
    float* __restrict__ out)
{
    __shared__ float t[32][33];
    int w0 = blockIdx.x * 32, c0 = blockIdx.y * 32;
    int bh = blockIdx.z;
    int b = bh / Hn, h = bh % Hn;
    int tx = threadIdx.x, ty = threadIdx.y;

    int c = c0 + tx;
    const float inv = 1.0f / (float)PIX;
    float mean = g_sum[c] * inv;
    float var  = g_sq[c] * inv - mean*mean;
    float rstd = rsqrtf(var + 1e-5f);
    float sc = gamma[c] * rstd;
    float sh = beta[c] - mean * sc;

    float v = g_y[((size_t)bh*Wn + (w0+ty))*Cn + c];
    t[ty][tx] = fmaxf(v*sc + sh, 0.f);
    __syncthreads();
    out[(((size_t)b*Cn + (c0+ty))*Hn + h)*Wn + (w0+tx)] = t[tx][ty];
}

// ---------------------------------------------------------------------------
extern "C" void kernel_launch(void* const* d_in, const int* in_sizes, int n_in,
                              void* d_out, int out_size)
{
    const float* x     = (const float*)d_in[0];
    const float* off_w = (const float*)d_in[1];
    const float* off_b = (const float*)d_in[2];
    const float* mod_w = (const float*)d_in[3];
    const float* mod_b = (const float*)d_in[4];
    const float* wmat  = (const float*)d_in[5];
    const float* bias  = (const float*)d_in[6];
    const float* gamma = (const float*)d_in[7];
    const float* beta  = (const float*)d_in[8];
    float* out = (float*)d_out;

    static int configured = 0;
    if (!configured) {
        cudaFuncSetAttribute(k_offmask, cudaFuncAttributeMaxDynamicSharedMemorySize, OSM);
        cudaFuncSetAttribute(k_deform,  cudaFuncAttributeMaxDynamicSharedMemorySize, DSM);
        configured = 1;
    }

    dim3 tgrid(Wn/32, Cn/32, Bn*Hn);
    dim3 tblk(32, 32);

    k_zero<<<1, 64>>>();
    k_wprep<<<64, 256>>>(wmat, off_w, mod_w);
    k_transpose_in<<<tgrid, tblk>>>(x);
    k_offmask<<<PIX/256, 512, OSM>>>(off_b, mod_b);
    k_deform <<<PIX/256, 256, DSM>>>(bias);
    k_norm_out<<<tgrid, tblk>>>(gamma, beta, out);
}

// round 10
// speedup vs baseline: 1.0380x; 1.0380x over previous
#include <cuda_runtime.h>
#include <cuda_bf16.h>
#include <math.h>
#include <cstdint>

#define Bn   8
#define Cn   64
#define Hn   128
#define Wn   128
#define PIX  (Bn*Hn*Wn)    // 131072

// offmask smem: aH 16384 | aL 16384 | wH 4096 | wL 4096
#define O_AL 16384
#define O_WH 32768
#define O_WL 36864
#define OSM  40960
// deform smem: aH0 aH1 aL0 aL1 (16KB each) | wH0 wH1 wL0 wL1 (8KB each) | psm0 psm1 (4KB each)
#define D_W0 65536
#define D_PS 98304
#define DSM  106496

// Scratch
__device__ float g_xt[PIX*Cn];            // x channels-last
__device__ float g_om[PIX*27];            // offsets+mask per pixel
__device__ float g_y [PIX*Cn];            // deform out [pix][c]
__device__ __nv_bfloat16 g_wdh[9*64*64];  // deform W hi   [tap][o][c]
__device__ __nv_bfloat16 g_wdl[9*64*64];  // deform W lo
__device__ __nv_bfloat16 g_woh[9*32*64];  // offmask W hi  [tap][o(32)][c]
__device__ __nv_bfloat16 g_wol[9*32*64];  // offmask W lo
__device__ float g_sum[Cn];
__device__ float g_sq [Cn];

#define MMA16816(d0,d1,d2,d3,a0,a1,a2,a3,b0,b1) \
    asm volatile("mma.sync.aligned.m16n8k16.row.col.f32.bf16.bf16.f32 " \
        "{%0,%1,%2,%3}, {%4,%5,%6,%7}, {%8,%9}, {%0,%1,%2,%3};" \
        : "+f"(d0), "+f"(d1), "+f"(d2), "+f"(d3) \
        : "r"(a0), "r"(a1), "r"(a2), "r"(a3), "r"(b0), "r"(b1))

#define LDSM4(r0,r1,r2,r3,a) \
    asm volatile("ldmatrix.sync.aligned.m8n8.x4.shared.b16 {%0,%1,%2,%3}, [%4];" \
        : "=r"(r0), "=r"(r1), "=r"(r2), "=r"(r3) : "r"(a))

#define BAR_WAIT(id,cnt) asm volatile("bar.sync %0, %1;"   :: "r"(id), "r"(cnt) : "memory")
#define BAR_SIG(id,cnt)  asm volatile("membar.cta;\n\tbar.arrive %0, %1;" :: "r"(id), "r"(cnt) : "memory")

__device__ __forceinline__ uint32_t lds_addr(const void* p) {
    return (uint32_t)__cvta_generic_to_shared(p);
}
__device__ __forceinline__ uint32_t pkbf(__nv_bfloat16 a, __nv_bfloat16 b) {
    uint32_t r;
    asm("mov.b32 %0, {%1, %2};" : "=r"(r)
        : "h"(__bfloat16_as_ushort(a)), "h"(__bfloat16_as_ushort(b)));
    return r;
}
__device__ __forceinline__ void split4(float4 v, uint2& hi, uint2& lo) {
    __nv_bfloat16 hx = __float2bfloat16_rn(v.x), hy = __float2bfloat16_rn(v.y);
    __nv_bfloat16 hz = __float2bfloat16_rn(v.z), hw = __float2bfloat16_rn(v.w);
    hi.x = pkbf(hx, hy); hi.y = pkbf(hz, hw);
    __nv_bfloat16 lx = __float2bfloat16_rn(v.x - __bfloat162float(hx));
    __nv_bfloat16 ly = __float2bfloat16_rn(v.y - __bfloat162float(hy));
    __nv_bfloat16 lz = __float2bfloat16_rn(v.z - __bfloat162float(hz));
    __nv_bfloat16 lw = __float2bfloat16_rn(v.w - __bfloat162float(hw));
    lo.x = pkbf(lx, ly); lo.y = pkbf(lz, lw);
}

// ---------------------------------------------------------------------------
__global__ void k_zero() {
    int i = threadIdx.x;
    if (i < Cn) { g_sum[i] = 0.f; g_sq[i] = 0.f; }
}

// ---------------------------------------------------------------------------
__global__ __launch_bounds__(256) void k_wprep(
    const float* __restrict__ wmat,
    const float* __restrict__ off_w, const float* __restrict__ mod_w)
{
    for (int i = blockIdx.x*256 + threadIdx.x; i < 9*4096 + 9*2048; i += gridDim.x*256) {
        if (i < 9*4096) {
            int tap = i >> 12, r = i & 4095;
            int o = r >> 6, c = r & 63;
            float v = wmat[(o*64 + c)*9 + tap];
            __nv_bfloat16 h = __float2bfloat16_rn(v);
            __nv_bfloat16 l = __float2bfloat16_rn(v - __bfloat162float(h));
            g_wdh[i] = h; g_wdl[i] = l;
        } else {
            int j = i - 9*4096;
            int tap = j >> 11, r = j & 2047;
            int o = r >> 6, c = r & 63;
            float v = 0.f;
            if (o < 18)      v = off_w[(o*64 + c)*9 + tap];
            else if (o < 27) v = mod_w[((o-18)*64 + c)*9 + tap];
            __nv_bfloat16 h = __float2bfloat16_rn(v);
            __nv_bfloat16 l = __float2bfloat16_rn(v - __bfloat162float(h));
            g_woh[j] = h; g_wol[j] = l;
        }
    }
}

// ---------------------------------------------------------------------------
__global__ __launch_bounds__(1024) void k_transpose_in(const float* __restrict__ x) {
    __shared__ float t[32][33];
    int w0 = blockIdx.x * 32, c0 = blockIdx.y * 32;
    int bh = blockIdx.z;
    int b = bh / Hn, h = bh % Hn;
    int tx = threadIdx.x, ty = threadIdx.y;
    t[ty][tx] = x[(((b*Cn) + (c0+ty))*Hn + h)*Wn + (w0+tx)];
    __syncthreads();
    g_xt[((size_t)bh*Wn + (w0+ty))*Cn + (c0+tx)] = t[tx][ty];
}

// ---------------------------------------------------------------------------
// offset/mask conv (R6 version): HMMA + ldmatrix + XOR swizzle, 256 thr.
__global__ __launch_bounds__(256) void k_offmask(
    const float* __restrict__ off_b, const float* __restrict__ mod_b)
{
    extern __shared__ __align__(16) char sm[];
    char* aH = sm;          char* aL = sm + O_AL;
    char* wH = sm + O_WH;   char* wL = sm + O_WL;
    uint32_t aHb = lds_addr(aH), aLb = lds_addr(aL);
    uint32_t wHb = lds_addr(wH), wLb = lds_addr(wL);

    int tid = threadIdx.x;
    int wid = tid >> 5, lane = tid & 31;
    int g = lane >> 2, tc = lane & 3;
    int lrow = lane & 7, lmat = lane >> 3;
    int blk = blockIdx.x;
    int b = blk >> 7, h = blk & 127;
    int p0 = blk * 128;
    int c4 = tid & 15, grp = tid >> 4;

    float dacc[4][4];
    #pragma unroll
    for (int n = 0; n < 4; n++)
        #pragma unroll
        for (int q = 0; q < 4; q++) dacc[n][q] = 0.f;

    int arow = wid*16 + ((lmat & 1) << 3) + lrow;
    uint32_t aRowOff = arow*128;
    int asw  = (arow & 7) << 4;
    int acol = (lmat >> 1) << 4;
    int browb = ((lmat >> 1) << 3) + lrow;
    int bsw  = (browb & 7) << 4;
    int bcol = (lmat & 1) << 4;

    for (int tap = 0; tap < 9; tap++) {
        __syncthreads();
        for (int i = tid; i < 256; i += 256) {
            int row = i >> 3, q = i & 7;
            int off = row*128 + ((q*16) ^ ((row & 7)*16));
            *(uint4*)(wH + off) = ((const uint4*)&g_woh[tap*2048])[i];
            *(uint4*)(wL + off) = ((const uint4*)&g_wol[tap*2048])[i];
        }
        int y = h + tap/3 - 1;
        int dxs = tap%3 - 1;
        #pragma unroll 4
        for (int it = 0; it < 8; it++) {
            int px = it*16 + grp;
            int xx = px + dxs;
            float4 v = make_float4(0.f,0.f,0.f,0.f);
            if (y >= 0 && y < Hn && xx >= 0 && xx < Wn)
                v = *(const float4*)&g_xt[(((size_t)b*Hn + y)*Wn + xx)*Cn + c4*4];
            uint2 hi, lo; split4(v, hi, lo);
            int off = px*128 + ((c4*8) ^ ((px & 7)*16));
            *(uint2*)(aH + off) = hi;
            *(uint2*)(aL + off) = lo;
        }
        __syncthreads();
        #pragma unroll
        for (int ks = 0; ks < 4; ks++) {
            uint32_t aoff = aRowOff + ((acol + ks*32) ^ asw);
            uint32_t ah0,ah1,ah2,ah3, al0,al1,al2,al3;
            LDSM4(ah0,ah1,ah2,ah3, aHb + aoff);
            LDSM4(al0,al1,al2,al3, aLb + aoff);
            #pragma unroll
            for (int np = 0; np < 2; np++) {
                uint32_t boff = (np*16 + browb)*128 + ((bcol + ks*32) ^ bsw);
                uint32_t bh0,bh1,bh2,bh3, bl0,bl1,bl2,bl3;
                LDSM4(bh0,bh1,bh2,bh3, wHb + boff);
                LDSM4(bl0,bl1,bl2,bl3, wLb + boff);
                MMA16816(dacc[2*np][0],dacc[2*np][1],dacc[2*np][2],dacc[2*np][3],
                         ah0,ah1,ah2,ah3, bh0,bh1);
                MMA16816(dacc[2*np][0],dacc[2*np][1],dacc[2*np][2],dacc[2*np][3],
                         al0,al1,al2,al3, bh0,bh1);
                MMA16816(dacc[2*np][0],dacc[2*np][1],dacc[2*np][2],dacc[2*np][3],
                         ah0,ah1,ah2,ah3, bl0,bl1);
                MMA16816(dacc[2*np+1][0],dacc[2*np+1][1],dacc[2*np+1][2],dacc[2*np+1][3],
                         ah0,ah1,ah2,ah3, bh2,bh3);
                MMA16816(dacc[2*np+1][0],dacc[2*np+1][1],dacc[2*np+1][2],dacc[2*np+1][3],
                         al0,al1,al2,al3, bh2,bh3);
                MMA16816(dacc[2*np+1][0],dacc[2*np+1][1],dacc[2*np+1][2],dacc[2*np+1][3],
                         ah0,ah1,ah2,ah3, bl2,bl3);
            }
        }
    }

    int px = p0 + wid*16 + g;
    #pragma unroll
    for (int nt = 0; nt < 4; nt++) {
        int o = nt*8 + 2*tc;
        if (o < 27) {
            float v0 = dacc[nt][0], v2 = dacc[nt][2];
            if (o < 18) { v0 += off_b[o]; v2 += off_b[o]; }
            else {
                v0 = 2.0f / (1.0f + expf(-(v0 + mod_b[o-18])));
                v2 = 2.0f / (1.0f + expf(-(v2 + mod_b[o-18])));
            }
            g_om[(size_t)px*27 + o]     = v0;
            g_om[(size_t)(px+8)*27 + o] = v2;
        }
        if (o+1 < 27) {
            float v1 = dacc[nt][1], v3 = dacc[nt][3];
            if (o+1 < 18) { v1 += off_b[o+1]; v3 += off_b[o+1]; }
            else {
                v1 = 2.0f / (1.0f + expf(-(v1 + mod_b[o+1-18])));
                v3 = 2.0f / (1.0f + expf(-(v3 + mod_b[o+1-18])));
            }
            g_om[(size_t)px*27 + o+1]     = v1;
            g_om[(size_t)(px+8)*27 + o+1] = v3;
        }
    }
}

// ---------------------------------------------------------------------------
// Deformable conv, WARP-SPECIALIZED: 512 thr, 128 px/block.
// Warps 0-7 produce; warps 8-15 consume. Signal side uses bar.arrive
// (non-blocking); wait side uses bar.sync. No deadlock cycle.
__global__ __launch_bounds__(512) void k_deform(const float* __restrict__ bias)
{
    extern __shared__ __align__(16) char sm[];
    uint32_t smb = lds_addr(sm);
    float* psm0 = (float*)(sm + D_PS);

    int tid = threadIdx.x;
    int wid = tid >> 5, lane = tid & 31;
    int blk = blockIdx.x;
    int b = blk >> 7, h = blk & 127;
    int p0 = blk * 128;

    float dacc[8][4];
    #pragma unroll
    for (int n = 0; n < 8; n++)
        #pragma unroll
        for (int q = 0; q < 4; q++) dacc[n][q] = 0.f;

    if (wid < 8) {
        // ------------------------------------------------ producers
        int ptid = tid;                 // 0..255
        int c4 = ptid & 15, grp = ptid >> 4;
        for (int tap = 0; tap < 9; tap++) {
            int s = tap & 1;
            int ky = tap/3, kx = tap - ky*3;
            char* aHs = sm + s*16384;
            char* aLs = sm + 32768 + s*16384;
            char* wHs = sm + D_W0 + s*8192;
            char* wLs = sm + D_W0 + 16384 + s*8192;
            float* psm = (float*)(sm + D_PS + s*4096);
            if (tap >= 2) BAR_WAIT(3 + s, 512);        // wait empty (blocking)
            // W stage
            #pragma unroll
            for (int i = 0; i < 2; i++) {
                int idx = ptid + i*256;
                int row = idx >> 3, q = idx & 7;
                int off = row*128 + ((q*16) ^ ((row & 7)*16));
                *(uint4*)(wHs + off) = ((const uint4*)&g_wdh[tap*4096])[idx];
                *(uint4*)(wLs + off) = ((const uint4*)&g_wdl[tap*4096])[idx];
            }
            // params: first 128 producer threads, one pixel each
            if (ptid < 128) {
                const float* omp = &g_om[(size_t)(p0 + ptid)*27];
                float dy = omp[tap*2], dx = omp[tap*2+1], mk = omp[18+tap];
                float py = (float)(h + ky - 1) + dy;
                float px_ = (float)(ptid + kx - 1) + dx;
                float fy = floorf(py), fx = floorf(px_);
                float ly = py - fy,    lx = px_ - fx;
                int y0 = (int)fy, x0 = (int)fx;
                int y1 = y0 + 1,  x1 = x0 + 1;
                float vy0 = (y0 >= 0 && y0 < Hn) ? 1.f : 0.f;
                float vy1 = (y1 >= 0 && y1 < Hn) ? 1.f : 0.f;
                float vx0 = (x0 >= 0 && x0 < Wn) ? 1.f : 0.f;
                float vx1 = (x1 >= 0 && x1 < Wn) ? 1.f : 0.f;
                int iy0 = min(max(y0,0),Hn-1), iy1 = min(max(y1,0),Hn-1);
                int ix0 = min(max(x0,0),Wn-1), ix1 = min(max(x1,0),Wn-1);
                int base = (b*Hn)*Wn;
                psm[ptid*8+0] = (1.f-ly)*(1.f-lx)*mk * vy0*vx0;
                psm[ptid*8+1] = (1.f-ly)*lx      *mk * vy0*vx1;
                psm[ptid*8+2] = ly      *(1.f-lx)*mk * vy1*vx0;
                psm[ptid*8+3] = ly      *lx      *mk * vy1*vx1;
                psm[ptid*8+4] = __int_as_float(((base + iy0*Wn + ix0)*Cn) >> 2);
                psm[ptid*8+5] = __int_as_float(((base + iy0*Wn + ix1)*Cn) >> 2);
                psm[ptid*8+6] = __int_as_float(((base + iy1*Wn + ix0)*Cn) >> 2);
                psm[ptid*8+7] = __int_as_float(((base + iy1*Wn + ix1)*Cn) >> 2);
            }
            BAR_WAIT(5, 256);                          // producers-only sync
            // gather (16 lanes/px)
            {
                const float4* P = (const float4*)g_xt;
                #pragma unroll 2
                for (int it = 0; it < 8; it++) {
                    int px = it*16 + grp;
                    float w00 = psm[px*8+0], w01 = psm[px*8+1];
                    float w10 = psm[px*8+2], w11 = psm[px*8+3];
                    int i00 = __float_as_int(psm[px*8+4]);
                    int i01 = __float_as_int(psm[px*8+5]);
                    int i10 = __float_as_int(psm[px*8+6]);
                    int i11 = __float_as_int(psm[px*8+7]);
                    float4 a = P[i00 + c4], e = P[i01 + c4];
                    float4 c = P[i10 + c4], d = P[i11 + c4];
                    float4 v;
                    v.x = w00*a.x + w01*e.x + w10*c.x + w11*d.x;
                    v.y = w00*a.y + w01*e.y + w10*c.y + w11*d.y;
                    v.z = w00*a.z + w01*e.z + w10*c.z + w11*d.z;
                    v.w = w00*a.w + w01*e.w + w10*c.w + w11*d.w;
                    uint2 hi, lo; split4(v, hi, lo);
                    int off = px*128 + ((c4*8) ^ ((px & 7)*16));
                    *(uint2*)(aHs + off) = hi;
                    *(uint2*)(aLs + off) = lo;
                }
            }
            BAR_SIG(1 + s, 512);                       // mark full (non-blocking)
        }
    } else {
        // ------------------------------------------------ consumers
        int cwid = wid - 8;                            // 0..7, 16 px each
        int lrow = lane & 7, lmat = lane >> 3;

        int arow = cwid*16 + ((lmat & 1) << 3) + lrow;
        uint32_t aRowOff = arow*128;
        int asw  = (arow & 7) << 4;
        int acol = (lmat >> 1) << 4;
        int browb = ((lmat >> 1) << 3) + lrow;
        int bsw  = (browb & 7) << 4;
        int bcol = (lmat & 1) << 4;

        for (int tap = 0; tap < 9; tap++) {
            int s = tap & 1;
            uint32_t aHb = smb + s*16384;
            uint32_t aLb = smb + 32768 + s*16384;
            uint32_t wHb = smb + D_W0 + s*8192;
            uint32_t wLb = smb + D_W0 + 16384 + s*8192;
            BAR_WAIT(1 + s, 512);                      // wait full (blocking)
            #pragma unroll
            for (int ks = 0; ks < 4; ks++) {
                uint32_t aoff = aRowOff + ((acol + ks*32) ^ asw);
                uint32_t ah0,ah1,ah2,ah3, al0,al1,al2,al3;
                LDSM4(ah0,ah1,ah2,ah3, aHb + aoff);
                LDSM4(al0,al1,al2,al3, aLb + aoff);
                #pragma unroll
                for (int np = 0; np < 4; np++) {
                    uint32_t boff = (np*16 + browb)*128 + ((bcol + ks*32) ^ bsw);
                    uint32_t bh0,bh1,bh2,bh3, bl0,bl1,bl2,bl3;
                    LDSM4(bh0,bh1,bh2,bh3, wHb + boff);
                    LDSM4(bl0,bl1,bl2,bl3, wLb + boff);
                    MMA16816(dacc[2*np][0],dacc[2*np][1],dacc[2*np][2],dacc[2*np][3],
                             ah0,ah1,ah2,ah3, bh0,bh1);
                    MMA16816(dacc[2*np][0],dacc[2*np][1],dacc[2*np][2],dacc[2*np][3],
                             al0,al1,al2,al3, bh0,bh1);
                    MMA16816(dacc[2*np][0],dacc[2*np][1],dacc[2*np][2],dacc[2*np][3],
                             ah0,ah1,ah2,ah3, bl0,bl1);
                    MMA16816(dacc[2*np+1][0],dacc[2*np+1][1],dacc[2*np+1][2],dacc[2*np+1][3],
                             ah0,ah1,ah2,ah3, bh2,bh3);
                    MMA16816(dacc[2*np+1][0],dacc[2*np+1][1],dacc[2*np+1][2],dacc[2*np+1][3],
                             al0,al1,al2,al3, bh2,bh3);
                    MMA16816(dacc[2*np+1][0],dacc[2*np+1][1],dacc[2*np+1][2],dacc[2*np+1][3],
                             ah0,ah1,ah2,ah3, bl2,bl3);
                }
            }
            if (tap <= 6) BAR_SIG(3 + s, 512);         // mark empty (non-blocking)
        }
    }

    // ---------------- uniform join ----------------
    __syncthreads();
    if (tid < 128) psm0[tid] = 0.f;
    __syncthreads();

    if (wid >= 8) {   // consumers: store + stats (no barriers inside)
        int cwid = wid - 8;
        int g = lane >> 2, tc = lane & 3;
        float ss[8], sh[8], qs[8], qh[8];
        int px = p0 + cwid*16 + g;
        #pragma unroll
        for (int nt = 0; nt < 8; nt++) {
            int o = nt*8 + 2*tc;
            float b0 = bias[o], b1 = bias[o+1];
            float v00 = dacc[nt][0] + b0, v01 = dacc[nt][1] + b1;
            float v10 = dacc[nt][2] + b0, v11 = dacc[nt][3] + b1;
            *(float2*)&g_y[(size_t)px*64 + o]     = make_float2(v00, v01);
            *(float2*)&g_y[(size_t)(px+8)*64 + o] = make_float2(v10, v11);
            ss[nt] = v00 + v10;        sh[nt] = v01 + v11;
            qs[nt] = v00*v00 + v10*v10; qh[nt] = v01*v01 + v11*v11;
        }
        #pragma unroll
        for (int d = 4; d < 32; d <<= 1) {
            #pragma unroll
            for (int nt = 0; nt < 8; nt++) {
                ss[nt] += __shfl_xor_sync(0xffffffffu, ss[nt], d);
                sh[nt] += __shfl_xor_sync(0xffffffffu, sh[nt], d);
                qs[nt] += __shfl_xor_sync(0xffffffffu, qs[nt], d);
                qh[nt] += __shfl_xor_sync(0xffffffffu, qh[nt], d);
            }
        }
        if (lane < 4) {
            #pragma unroll
            for (int nt = 0; nt < 8; nt++) {
                int o = nt*8 + 2*tc;
                atomicAdd(&psm0[o],      ss[nt]);
                atomicAdd(&psm0[o+1],    sh[nt]);
                atomicAdd(&psm0[64+o],   qs[nt]);
                atomicAdd(&psm0[64+o+1], qh[nt]);
            }
        }
    }

    __syncthreads();
    if (tid < 64) {
        atomicAdd(&g_sum[tid], psm0[tid]);
        atomicAdd(&g_sq [tid], psm0[64+tid]);
    }
}

// ---------------------------------------------------------------------------
__global__ __launch_bounds__(1024) void k_norm_out(
    const float* __restrict__ gamma, const float* __restrict__ beta,
    float* __restrict__ out)
{
    __shared__ float t[32][33];
    int w0 = blockIdx.x * 32, c0 = blockIdx.y * 32;
    int bh = blockIdx.z;
    int b = bh / Hn, h = bh % Hn;
    int tx = threadIdx.x, ty = threadIdx.y;

    int c = c0 + tx;
    const float inv = 1.0f / (float)PIX;
    float mean = g_sum[c] * inv;
    float var  = g_sq[c] * inv - mean*mean;
    float rstd = rsqrtf(var + 1e-5f);
    float sc = gamma[c] * rstd;
    float sh = beta[c] - mean * sc;

    float v = g_y[((size_t)bh*Wn + (w0+ty))*Cn + c];
    t[ty][tx] = fmaxf(v*sc + sh, 0.f);
    __syncthreads();
    out[(((size_t)b*Cn + (c0+ty))*Hn + h)*Wn + (w0+tx)] = t[tx][ty];
}

// ---------------------------------------------------------------------------
extern "C" void kernel_launch(void* const* d_in, const int* in_sizes, int n_in,
                              void* d_out, int out_size)
{
    const float* x     = (const float*)d_in[0];
    const float* off_w = (const float*)d_in[1];
    const float* off_b = (const float*)d_in[2];
    const float* mod_w = (const float*)d_in[3];
    const float* mod_b = (const float*)d_in[4];
    const float* wmat  = (const float*)d_in[5];
    const float* bias  = (const float*)d_in[6];
    const float* gamma = (const float*)d_in[7];
    const float* beta  = (const float*)d_in[8];
    float* out = (float*)d_out;

    static int configured = 0;
    if (!configured) {
        cudaFuncSetAttribute(k_offmask, cudaFuncAttributeMaxDynamicSharedMemorySize, OSM);
        cudaFuncSetAttribute(k_deform,  cudaFuncAttributeMaxDynamicSharedMemorySize, DSM);
        configured = 1;
    }

    dim3 tgrid(Wn/32, Cn/32, Bn*Hn);
    dim3 tblk(32, 32);

    k_zero<<<1, 64>>>();
    k_wprep<<<64, 256>>>(wmat, off_w, mod_w);
    k_transpose_in<<<tgrid, tblk>>>(x);
    k_offmask<<<PIX/128, 256, OSM>>>(off_b, mod_b);
    k_deform <<<PIX/128, 512, DSM>>>(bias);
    k_norm_out<<<tgrid, tblk>>>(gamma, beta, out);
}

// round 11
// speedup vs baseline: 1.1891x; 1.1456x over previous
#include <cuda_runtime.h>
#include <cuda_bf16.h>
#include <math.h>
#include <cstdint>

#define Bn   8
#define Cn   64
#define Hn   128
#define Wn   128
#define PIX  (Bn*Hn*Wn)    // 131072

// offmask smem: aH 16384 | aL 16384 | wH 4096 | wL 4096
#define O_AL 16384
#define O_WH 32768
#define O_WL 36864
#define OSM  40960
// deform smem (double buffered):
// aH0 aH1 (16K each) | aL0 aL1 (16K each) | wH0 wH1 (8K each) | wL0 wL1 (8K each) | psm0 psm1 (4K each)
#define D_AL  32768
#define D_WH  65536
#define D_WL  81920
#define D_PS  98304
#define DSM   106496

// Scratch
__device__ float g_xt[PIX*Cn];            // x channels-last
__device__ float g_om[PIX*27];            // offsets+mask per pixel
__device__ float g_y [PIX*Cn];            // deform out [pix][c]
__device__ __nv_bfloat16 g_wdh[9*64*64];  // deform W hi   [tap][o][c]
__device__ __nv_bfloat16 g_wdl[9*64*64];  // deform W lo
__device__ __nv_bfloat16 g_woh[9*32*64];  // offmask W hi  [tap][o(32)][c]
__device__ __nv_bfloat16 g_wol[9*32*64];  // offmask W lo
__device__ float g_sum[Cn];
__device__ float g_sq [Cn];

#define MMA16816(d0,d1,d2,d3,a0,a1,a2,a3,b0,b1) \
    asm volatile("mma.sync.aligned.m16n8k16.row.col.f32.bf16.bf16.f32 " \
        "{%0,%1,%2,%3}, {%4,%5,%6,%7}, {%8,%9}, {%0,%1,%2,%3};" \
        : "+f"(d0), "+f"(d1), "+f"(d2), "+f"(d3) \
        : "r"(a0), "r"(a1), "r"(a2), "r"(a3), "r"(b0), "r"(b1))

#define LDSM4(r0,r1,r2,r3,a) \
    asm volatile("ldmatrix.sync.aligned.m8n8.x4.shared.b16 {%0,%1,%2,%3}, [%4];" \
        : "=r"(r0), "=r"(r1), "=r"(r2), "=r"(r3) : "r"(a))

__device__ __forceinline__ uint32_t lds_addr(const void* p) {
    return (uint32_t)__cvta_generic_to_shared(p);
}
__device__ __forceinline__ uint32_t pkbf(__nv_bfloat16 a, __nv_bfloat16 b) {
    uint32_t r;
    asm("mov.b32 %0, {%1, %2};" : "=r"(r)
        : "h"(__bfloat16_as_ushort(a)), "h"(__bfloat16_as_ushort(b)));
    return r;
}
__device__ __forceinline__ void split4(float4 v, uint2& hi, uint2& lo) {
    __nv_bfloat16 hx = __float2bfloat16_rn(v.x), hy = __float2bfloat16_rn(v.y);
    __nv_bfloat16 hz = __float2bfloat16_rn(v.z), hw = __float2bfloat16_rn(v.w);
    hi.x = pkbf(hx, hy); hi.y = pkbf(hz, hw);
    __nv_bfloat16 lx = __float2bfloat16_rn(v.x - __bfloat162float(hx));
    __nv_bfloat16 ly = __float2bfloat16_rn(v.y - __bfloat162float(hy));
    __nv_bfloat16 lz = __float2bfloat16_rn(v.z - __bfloat162float(hz));
    __nv_bfloat16 lw = __float2bfloat16_rn(v.w - __bfloat162float(hw));
    lo.x = pkbf(lx, ly); lo.y = pkbf(lz, lw);
}

// ---------------------------------------------------------------------------
__global__ void k_zero() {
    int i = threadIdx.x;
    if (i < Cn) { g_sum[i] = 0.f; g_sq[i] = 0.f; }
}

// ---------------------------------------------------------------------------
__global__ __launch_bounds__(256) void k_wprep(
    const float* __restrict__ wmat,
    const float* __restrict__ off_w, const float* __restrict__ mod_w)
{
    for (int i = blockIdx.x*256 + threadIdx.x; i < 9*4096 + 9*2048; i += gridDim.x*256) {
        if (i < 9*4096) {
            int tap = i >> 12, r = i & 4095;
            int o = r >> 6, c = r & 63;
            float v = wmat[(o*64 + c)*9 + tap];
            __nv_bfloat16 h = __float2bfloat16_rn(v);
            __nv_bfloat16 l = __float2bfloat16_rn(v - __bfloat162float(h));
            g_wdh[i] = h; g_wdl[i] = l;
        } else {
            int j = i - 9*4096;
            int tap = j >> 11, r = j & 2047;
            int o = r >> 6, c = r & 63;
            float v = 0.f;
            if (o < 18)      v = off_w[(o*64 + c)*9 + tap];
            else if (o < 27) v = mod_w[((o-18)*64 + c)*9 + tap];
            __nv_bfloat16 h = __float2bfloat16_rn(v);
            __nv_bfloat16 l = __float2bfloat16_rn(v - __bfloat162float(h));
            g_woh[j] = h; g_wol[j] = l;
        }
    }
}

// ---------------------------------------------------------------------------
__global__ __launch_bounds__(1024) void k_transpose_in(const float* __restrict__ x) {
    __shared__ float t[32][33];
    int w0 = blockIdx.x * 32, c0 = blockIdx.y * 32;
    int bh = blockIdx.z;
    int b = bh / Hn, h = bh % Hn;
    int tx = threadIdx.x, ty = threadIdx.y;
    t[ty][tx] = x[(((b*Cn) + (c0+ty))*Hn + h)*Wn + (w0+tx)];
    __syncthreads();
    g_xt[((size_t)bh*Wn + (w0+ty))*Cn + (c0+tx)] = t[tx][ty];
}

// ---------------------------------------------------------------------------
// offset/mask conv (R6 version, known 79us): HMMA + ldmatrix + XOR swizzle.
__global__ __launch_bounds__(256) void k_offmask(
    const float* __restrict__ off_b, const float* __restrict__ mod_b)
{
    extern __shared__ __align__(16) char sm[];
    char* aH = sm;          char* aL = sm + O_AL;
    char* wH = sm + O_WH;   char* wL = sm + O_WL;
    uint32_t aHb = lds_addr(aH), aLb = lds_addr(aL);
    uint32_t wHb = lds_addr(wH), wLb = lds_addr(wL);

    int tid = threadIdx.x;
    int wid = tid >> 5, lane = tid & 31;
    int g = lane >> 2, tc = lane & 3;
    int lrow = lane & 7, lmat = lane >> 3;
    int blk = blockIdx.x;
    int b = blk >> 7, h = blk & 127;
    int p0 = blk * 128;
    int c4 = tid & 15, grp = tid >> 4;

    float dacc[4][4];
    #pragma unroll
    for (int n = 0; n < 4; n++)
        #pragma unroll
        for (int q = 0; q < 4; q++) dacc[n][q] = 0.f;

    int arow = wid*16 + ((lmat & 1) << 3) + lrow;
    uint32_t aRowOff = arow*128;
    int asw  = (arow & 7) << 4;
    int acol = (lmat >> 1) << 4;
    int browb = ((lmat >> 1) << 3) + lrow;
    int bsw  = (browb & 7) << 4;
    int bcol = (lmat & 1) << 4;

    for (int tap = 0; tap < 9; tap++) {
        __syncthreads();
        for (int i = tid; i < 256; i += 256) {
            int row = i >> 3, q = i & 7;
            int off = row*128 + ((q*16) ^ ((row & 7)*16));
            *(uint4*)(wH + off) = ((const uint4*)&g_woh[tap*2048])[i];
            *(uint4*)(wL + off) = ((const uint4*)&g_wol[tap*2048])[i];
        }
        int y = h + tap/3 - 1;
        int dxs = tap%3 - 1;
        #pragma unroll 4
        for (int it = 0; it < 8; it++) {
            int px = it*16 + grp;
            int xx = px + dxs;
            float4 v = make_float4(0.f,0.f,0.f,0.f);
            if (y >= 0 && y < Hn && xx >= 0 && xx < Wn)
                v = *(const float4*)&g_xt[(((size_t)b*Hn + y)*Wn + xx)*Cn + c4*4];
            uint2 hi, lo; split4(v, hi, lo);
            int off = px*128 + ((c4*8) ^ ((px & 7)*16));
            *(uint2*)(aH + off) = hi;
            *(uint2*)(aL + off) = lo;
        }
        __syncthreads();
        #pragma unroll
        for (int ks = 0; ks < 4; ks++) {
            uint32_t aoff = aRowOff + ((acol + ks*32) ^ asw);
            uint32_t ah0,ah1,ah2,ah3, al0,al1,al2,al3;
            LDSM4(ah0,ah1,ah2,ah3, aHb + aoff);
            LDSM4(al0,al1,al2,al3, aLb + aoff);
            #pragma unroll
            for (int np = 0; np < 2; np++) {
                uint32_t boff = (np*16 + browb)*128 + ((bcol + ks*32) ^ bsw);
                uint32_t bh0,bh1,bh2,bh3, bl0,bl1,bl2,bl3;
                LDSM4(bh0,bh1,bh2,bh3, wHb + boff);
                LDSM4(bl0,bl1,bl2,bl3, wLb + boff);
                MMA16816(dacc[2*np][0],dacc[2*np][1],dacc[2*np][2],dacc[2*np][3],
                         ah0,ah1,ah2,ah3, bh0,bh1);
                MMA16816(dacc[2*np][0],dacc[2*np][1],dacc[2*np][2],dacc[2*np][3],
                         al0,al1,al2,al3, bh0,bh1);
                MMA16816(dacc[2*np][0],dacc[2*np][1],dacc[2*np][2],dacc[2*np][3],
                         ah0,ah1,ah2,ah3, bl0,bl1);
                MMA16816(dacc[2*np+1][0],dacc[2*np+1][1],dacc[2*np+1][2],dacc[2*np+1][3],
                         ah0,ah1,ah2,ah3, bh2,bh3);
                MMA16816(dacc[2*np+1][0],dacc[2*np+1][1],dacc[2*np+1][2],dacc[2*np+1][3],
                         al0,al1,al2,al3, bh2,bh3);
                MMA16816(dacc[2*np+1][0],dacc[2*np+1][1],dacc[2*np+1][2],dacc[2*np+1][3],
                         ah0,ah1,ah2,ah3, bl2,bl3);
            }
        }
    }

    int px = p0 + wid*16 + g;
    #pragma unroll
    for (int nt = 0; nt < 4; nt++) {
        int o = nt*8 + 2*tc;
        if (o < 27) {
            float v0 = dacc[nt][0], v2 = dacc[nt][2];
            if (o < 18) { v0 += off_b[o]; v2 += off_b[o]; }
            else {
                v0 = 2.0f / (1.0f + expf(-(v0 + mod_b[o-18])));
                v2 = 2.0f / (1.0f + expf(-(v2 + mod_b[o-18])));
            }
            g_om[(size_t)px*27 + o]     = v0;
            g_om[(size_t)(px+8)*27 + o] = v2;
        }
        if (o+1 < 27) {
            float v1 = dacc[nt][1], v3 = dacc[nt][3];
            if (o+1 < 18) { v1 += off_b[o+1]; v3 += off_b[o+1]; }
            else {
                v1 = 2.0f / (1.0f + expf(-(v1 + mod_b[o+1-18])));
                v3 = 2.0f / (1.0f + expf(-(v3 + mod_b[o+1-18])));
            }
            g_om[(size_t)px*27 + o+1]     = v1;
            g_om[(size_t)(px+8)*27 + o+1] = v3;
        }
    }
}

// ---------------------------------------------------------------------------
// Deformable conv, homogeneous DOUBLE-BUFFERED pipeline: 256 thr, 128 px.
// Per tap: ONE __syncthreads; then MMA(buf s) followed by stage(buf s^1).
// Params pipelined two taps ahead (no intra-phase sync needed).
__global__ __launch_bounds__(256) void k_deform(const float* __restrict__ bias)
{
    extern __shared__ __align__(16) char sm[];
    uint32_t smb = lds_addr(sm);

    int tid = threadIdx.x;
    int wid = tid >> 5, lane = tid & 31;
    int blk = blockIdx.x;
    int b = blk >> 7, h = blk & 127;
    int p0 = blk * 128;
    int c4 = tid & 15, grp = tid >> 4;

    float dacc[8][4];
    #pragma unroll
    for (int n = 0; n < 8; n++)
        #pragma unroll
        for (int q = 0; q < 4; q++) dacc[n][q] = 0.f;

    // MMA addressing (R6 layout)
    int g = lane >> 2, tc = lane & 3;
    int lrow = lane & 7, lmat = lane >> 3;
    int arow = wid*16 + ((lmat & 1) << 3) + lrow;
    uint32_t aRowOff = arow*128;
    int asw  = (arow & 7) << 4;
    int acol = (lmat >> 1) << 4;
    int browb = ((lmat >> 1) << 3) + lrow;
    int bsw  = (browb & 7) << 4;
    int bcol = (lmat & 1) << 4;

    auto calc_params = [&](int tap, int s) {
        if (tid < 128) {
            float* psm = (float*)(sm + D_PS + s*4096);
            const float* omp = &g_om[(size_t)(p0 + tid)*27];
            int ky = tap/3, kx = tap - ky*3;
            float dy = omp[tap*2], dx = omp[tap*2+1], mk = omp[18+tap];
            float py = (float)(h + ky - 1) + dy;
            float px_ = (float)(tid + kx - 1) + dx;
            float fy = floorf(py), fx = floorf(px_);
            float ly = py - fy,    lx = px_ - fx;
            int y0 = (int)fy, x0 = (int)fx;
            int y1 = y0 + 1,  x1 = x0 + 1;
            float vy0 = (y0 >= 0 && y0 < Hn) ? 1.f : 0.f;
            float vy1 = (y1 >= 0 && y1 < Hn) ? 1.f : 0.f;
            float vx0 = (x0 >= 0 && x0 < Wn) ? 1.f : 0.f;
            float vx1 = (x1 >= 0 && x1 < Wn) ? 1.f : 0.f;
            int iy0 = min(max(y0,0),Hn-1), iy1 = min(max(y1,0),Hn-1);
            int ix0 = min(max(x0,0),Wn-1), ix1 = min(max(x1,0),Wn-1);
            int base = (b*Hn)*Wn;
            psm[tid*8+0] = (1.f-ly)*(1.f-lx)*mk * vy0*vx0;
            psm[tid*8+1] = (1.f-ly)*lx      *mk * vy0*vx1;
            psm[tid*8+2] = ly      *(1.f-lx)*mk * vy1*vx0;
            psm[tid*8+3] = ly      *lx      *mk * vy1*vx1;
            psm[tid*8+4] = __int_as_float(((base + iy0*Wn + ix0)*Cn) >> 2);
            psm[tid*8+5] = __int_as_float(((base + iy0*Wn + ix1)*Cn) >> 2);
            psm[tid*8+6] = __int_as_float(((base + iy1*Wn + ix0)*Cn) >> 2);
            psm[tid*8+7] = __int_as_float(((base + iy1*Wn + ix1)*Cn) >> 2);
        }
    };
    auto stage_w = [&](int tap, int s) {
        char* wHs = sm + D_WH + s*8192;
        char* wLs = sm + D_WL + s*8192;
        #pragma unroll
        for (int i = 0; i < 2; i++) {
            int idx = tid + i*256;
            int row = idx >> 3, q = idx & 7;
            int off = row*128 + ((q*16) ^ ((row & 7)*16));
            *(uint4*)(wHs + off) = ((const uint4*)&g_wdh[tap*4096])[idx];
            *(uint4*)(wLs + off) = ((const uint4*)&g_wdl[tap*4096])[idx];
        }
    };
    auto do_gather = [&](int s) {
        char* aHs = sm + s*16384;
        char* aLs = sm + D_AL + s*16384;
        const float* psm = (const float*)(sm + D_PS + s*4096);
        const float4* P = (const float4*)g_xt;
        #pragma unroll 2
        for (int it = 0; it < 8; it++) {
            int px = it*16 + grp;
            float w00 = psm[px*8+0], w01 = psm[px*8+1];
            float w10 = psm[px*8+2], w11 = psm[px*8+3];
            int i00 = __float_as_int(psm[px*8+4]);
            int i01 = __float_as_int(psm[px*8+5]);
            int i10 = __float_as_int(psm[px*8+6]);
            int i11 = __float_as_int(psm[px*8+7]);
            float4 a = P[i00 + c4], e = P[i01 + c4];
            float4 c = P[i10 + c4], d = P[i11 + c4];
            float4 v;
            v.x = w00*a.x + w01*e.x + w10*c.x + w11*d.x;
            v.y = w00*a.y + w01*e.y + w10*c.y + w11*d.y;
            v.z = w00*a.z + w01*e.z + w10*c.z + w11*d.z;
            v.w = w00*a.w + w01*e.w + w10*c.w + w11*d.w;
            uint2 hi, lo; split4(v, hi, lo);
            int off = px*128 + ((c4*8) ^ ((px & 7)*16));
            *(uint2*)(aHs + off) = hi;
            *(uint2*)(aLs + off) = lo;
        }
    };
    auto do_mma = [&](int s) {
        uint32_t aHb = smb + s*16384;
        uint32_t aLb = smb + D_AL + s*16384;
        uint32_t wHb = smb + D_WH + s*8192;
        uint32_t wLb = smb + D_WL + s*8192;
        #pragma unroll
        for (int ks = 0; ks < 4; ks++) {
            uint32_t aoff = aRowOff + ((acol + ks*32) ^ asw);
            uint32_t ah0,ah1,ah2,ah3, al0,al1,al2,al3;
            LDSM4(ah0,ah1,ah2,ah3, aHb + aoff);
            LDSM4(al0,al1,al2,al3, aLb + aoff);
            #pragma unroll
            for (int np = 0; np < 4; np++) {
                uint32_t boff = (np*16 + browb)*128 + ((bcol + ks*32) ^ bsw);
                uint32_t bh0,bh1,bh2,bh3, bl0,bl1,bl2,bl3;
                LDSM4(bh0,bh1,bh2,bh3, wHb + boff);
                LDSM4(bl0,bl1,bl2,bl3, wLb + boff);
                MMA16816(dacc[2*np][0],dacc[2*np][1],dacc[2*np][2],dacc[2*np][3],
                         ah0,ah1,ah2,ah3, bh0,bh1);
                MMA16816(dacc[2*np][0],dacc[2*np][1],dacc[2*np][2],dacc[2*np][3],
                         al0,al1,al2,al3, bh0,bh1);
                MMA16816(dacc[2*np][0],dacc[2*np][1],dacc[2*np][2],dacc[2*np][3],
                         ah0,ah1,ah2,ah3, bl0,bl1);
                MMA16816(dacc[2*np+1][0],dacc[2*np+1][1],dacc[2*np+1][2],dacc[2*np+1][3],
                         ah0,ah1,ah2,ah3, bh2,bh3);
                MMA16816(dacc[2*np+1][0],dacc[2*np+1][1],dacc[2*np+1][2],dacc[2*np+1][3],
                         al0,al1,al2,al3, bh2,bh3);
                MMA16816(dacc[2*np+1][0],dacc[2*np+1][1],dacc[2*np+1][2],dacc[2*np+1][3],
                         ah0,ah1,ah2,ah3, bl2,bl3);
            }
        }
    };

    // Prologue: params for taps 0 and 1, W_0; then gather_0
    calc_params(0, 0);
    calc_params(1, 1);
    stage_w(0, 0);
    __syncthreads();
    do_gather(0);

    // Pipelined mainloop: ONE sync per tap
    for (int tap = 0; tap < 9; tap++) {
        int s = tap & 1;
        __syncthreads();
        do_mma(s);
        if (tap < 8) {
            stage_w(tap + 1, s ^ 1);
            do_gather(s ^ 1);                 // reads psm[s^1] = params(tap+1)
            if (tap < 7) calc_params(tap + 2, s);
        }
    }

    // Epilogue: +bias, store y, fused BN stats (block-uniform barriers only)
    float* psm0 = (float*)(sm + D_PS);
    __syncthreads();
    if (tid < 128) psm0[tid] = 0.f;
    __syncthreads();

    float ss[8], sh[8], qs[8], qh[8];
    int px = p0 + wid*16 + g;
    #pragma unroll
    for (int nt = 0; nt < 8; nt++) {
        int o = nt*8 + 2*tc;
        float b0 = bias[o], b1 = bias[o+1];
        float v00 = dacc[nt][0] + b0, v01 = dacc[nt][1] + b1;
        float v10 = dacc[nt][2] + b0, v11 = dacc[nt][3] + b1;
        *(float2*)&g_y[(size_t)px*64 + o]     = make_float2(v00, v01);
        *(float2*)&g_y[(size_t)(px+8)*64 + o] = make_float2(v10, v11);
        ss[nt] = v00 + v10;        sh[nt] = v01 + v11;
        qs[nt] = v00*v00 + v10*v10; qh[nt] = v01*v01 + v11*v11;
    }
    #pragma unroll
    for (int d = 4; d < 32; d <<= 1) {
        #pragma unroll
        for (int nt = 0; nt < 8; nt++) {
            ss[nt] += __shfl_xor_sync(0xffffffffu, ss[nt], d);
            sh[nt] += __shfl_xor_sync(0xffffffffu, sh[nt], d);
            qs[nt] += __shfl_xor_sync(0xffffffffu, qs[nt], d);
            qh[nt] += __shfl_xor_sync(0xffffffffu, qh[nt], d);
        }
    }
    if (lane < 4) {
        #pragma unroll
        for (int nt = 0; nt < 8; nt++) {
            int o = nt*8 + 2*tc;
            atomicAdd(&psm0[o],      ss[nt]);
            atomicAdd(&psm0[o+1],    sh[nt]);
            atomicAdd(&psm0[64+o],   qs[nt]);
            atomicAdd(&psm0[64+o+1], qh[nt]);
        }
    }
    __syncthreads();
    if (tid < 64) {
        atomicAdd(&g_sum[tid], psm0[tid]);
        atomicAdd(&g_sq [tid], psm0[64+tid]);
    }
}

// ---------------------------------------------------------------------------
__global__ __launch_bounds__(1024) void k_norm_out(
    const float* __restrict__ gamma, const float* __restrict__ beta,
    float* __restrict__ out)
{
    __shared__ float t[32][33];
    int w0 = blockIdx.x * 32, c0 = blockIdx.y * 32;
    int bh = blockIdx.z;
    int b = bh / Hn, h = bh % Hn;
    int tx = threadIdx.x, ty = threadIdx.y;

    int c = c0 + tx;
    const float inv = 1.0f / (float)PIX;
    float mean = g_sum[c] * inv;
    float var  = g_sq[c] * inv - mean*mean;
    float rstd = rsqrtf(var + 1e-5f);
    float sc = gamma[c] * rstd;
    float sh = beta[c] - mean * sc;

    float v = g_y[((size_t)bh*Wn + (w0+ty))*Cn + c];
    t[ty][tx] = fmaxf(v*sc + sh, 0.f);
    __syncthreads();
    out[(((size_t)b*Cn + (c0+ty))*Hn + h)*Wn + (w0+tx)] = t[tx][ty];
}

// ---------------------------------------------------------------------------
extern "C" void kernel_launch(void* const* d_in, const int* in_sizes, int n_in,
                              void* d_out, int out_size)
{
    const float* x     = (const float*)d_in[0];
    const float* off_w = (const float*)d_in[1];
    const float* off_b = (const float*)d_in[2];
    const float* mod_w = (const float*)d_in[3];
    const float* mod_b = (const float*)d_in[4];
    const float* wmat  = (const float*)d_in[5];
    const float* bias  = (const float*)d_in[6];
    const float* gamma = (const float*)d_in[7];
    const float* beta  = (const float*)d_in[8];
    float* out = (float*)d_out;

    static int configured = 0;
    if (!configured) {
        cudaFuncSetAttribute(k_offmask, cudaFuncAttributeMaxDynamicSharedMemorySize, OSM);
        cudaFuncSetAttribute(k_deform,  cudaFuncAttributeMaxDynamicSharedMemorySize, DSM);
        configured = 1;
    }

    dim3 tgrid(Wn/32, Cn/32, Bn*Hn);
    dim3 tblk(32, 32);

    k_zero<<<1, 64>>>();
    k_wprep<<<64, 256>>>(wmat, off_w, mod_w);
    k_transpose_in<<<tgrid, tblk>>>(x);
    k_offmask<<<PIX/128, 256, OSM>>>(off_b, mod_b);
    k_deform <<<PIX/128, 256, DSM>>>(bias);
    k_norm_out<<<tgrid, tblk>>>(gamma, beta, out);
}

// round 12
// speedup vs baseline: 1.3003x; 1.0936x over previous
#include <cuda_runtime.h>
#include <cuda_fp16.h>
#include <math.h>
#include <cstdint>

#define Bn   8
#define Cn   64
#define Hn   128
#define Wn   128
#define PIX  (Bn*Hn*Wn)    // 131072

// offmask smem: aH 16384 | aL 16384 | wH 4096
#define O_AL 16384
#define O_WH 32768
#define OSM  36864
// deform smem: aH 16384 | aL 16384 | wH 8192 | psm 4096
#define D_AL 16384
#define D_WH 32768
#define D_PS 40960
#define DSM  45056

// Scratch
__device__ float g_xt[PIX*Cn];            // x channels-last
__device__ float g_om[PIX*27];            // offsets+mask per pixel
__device__ float g_y [PIX*Cn];            // deform out [pix][c]
__device__ __half g_wdh[9*64*64];         // deform W fp16  [tap][o][c]
__device__ __half g_woh[9*32*64];         // offmask W fp16 [tap][o(32)][c]
__device__ float g_sum[Cn];
__device__ float g_sq [Cn];

#define MMA16816(d0,d1,d2,d3,a0,a1,a2,a3,b0,b1) \
    asm volatile("mma.sync.aligned.m16n8k16.row.col.f32.f16.f16.f32 " \
        "{%0,%1,%2,%3}, {%4,%5,%6,%7}, {%8,%9}, {%0,%1,%2,%3};" \
        : "+f"(d0), "+f"(d1), "+f"(d2), "+f"(d3) \
        : "r"(a0), "r"(a1), "r"(a2), "r"(a3), "r"(b0), "r"(b1))

#define LDSM4(r0,r1,r2,r3,a) \
    asm volatile("ldmatrix.sync.aligned.m8n8.x4.shared.b16 {%0,%1,%2,%3}, [%4];" \
        : "=r"(r0), "=r"(r1), "=r"(r2), "=r"(r3) : "r"(a))

__device__ __forceinline__ uint32_t lds_addr(const void* p) {
    return (uint32_t)__cvta_generic_to_shared(p);
}
__device__ __forceinline__ uint32_t pkhf(__half a, __half b) {
    uint32_t r;
    asm("mov.b32 %0, {%1, %2};" : "=r"(r)
        : "h"(__half_as_ushort(a)), "h"(__half_as_ushort(b)));
    return r;
}
// split float4 into fp16 hi + fp16 residual lo (packed pairs)
__device__ __forceinline__ void split4(float4 v, uint2& hi, uint2& lo) {
    __half hx = __float2half_rn(v.x), hy = __float2half_rn(v.y);
    __half hz = __float2half_rn(v.z), hw = __float2half_rn(v.w);
    hi.x = pkhf(hx, hy); hi.y = pkhf(hz, hw);
    __half lx = __float2half_rn(v.x - __half2float(hx));
    __half ly = __float2half_rn(v.y - __half2float(hy));
    __half lz = __float2half_rn(v.z - __half2float(hz));
    __half lw = __float2half_rn(v.w - __half2float(hw));
    lo.x = pkhf(lx, ly); lo.y = pkhf(lz, lw);
}

// ---------------------------------------------------------------------------
__global__ void k_zero() {
    int i = threadIdx.x;
    if (i < Cn) { g_sum[i] = 0.f; g_sq[i] = 0.f; }
}

// ---------------------------------------------------------------------------
// Weight prep: fp16 (hi only — weight residual term dropped by design).
__global__ __launch_bounds__(256) void k_wprep(
    const float* __restrict__ wmat,
    const float* __restrict__ off_w, const float* __restrict__ mod_w)
{
    for (int i = blockIdx.x*256 + threadIdx.x; i < 9*4096 + 9*2048; i += gridDim.x*256) {
        if (i < 9*4096) {
            int tap = i >> 12, r = i & 4095;
            int o = r >> 6, c = r & 63;
            g_wdh[i] = __float2half_rn(wmat[(o*64 + c)*9 + tap]);
        } else {
            int j = i - 9*4096;
            int tap = j >> 11, r = j & 2047;
            int o = r >> 6, c = r & 63;
            float v = 0.f;
            if (o < 18)      v = off_w[(o*64 + c)*9 + tap];
            else if (o < 27) v = mod_w[((o-18)*64 + c)*9 + tap];
            g_woh[j] = __float2half_rn(v);
        }
    }
}

// ---------------------------------------------------------------------------
__global__ __launch_bounds__(1024) void k_transpose_in(const float* __restrict__ x) {
    __shared__ float t[32][33];
    int w0 = blockIdx.x * 32, c0 = blockIdx.y * 32;
    int bh = blockIdx.z;
    int b = bh / Hn, h = bh % Hn;
    int tx = threadIdx.x, ty = threadIdx.y;
    t[ty][tx] = x[(((b*Cn) + (c0+ty))*Hn + h)*Wn + (w0+tx)];
    __syncthreads();
    g_xt[((size_t)bh*Wn + (w0+ty))*Cn + (c0+tx)] = t[tx][ty];
}

// ---------------------------------------------------------------------------
// offset/mask conv: HMMA fp16 2-term + ldmatrix + XOR swizzle, 256 thr.
__global__ __launch_bounds__(256) void k_offmask(
    const float* __restrict__ off_b, const float* __restrict__ mod_b)
{
    extern __shared__ __align__(16) char sm[];
    char* aH = sm;          char* aL = sm + O_AL;
    char* wH = sm + O_WH;
    uint32_t aHb = lds_addr(aH), aLb = lds_addr(aL);
    uint32_t wHb = lds_addr(wH);

    int tid = threadIdx.x;
    int wid = tid >> 5, lane = tid & 31;
    int g = lane >> 2, tc = lane & 3;
    int lrow = lane & 7, lmat = lane >> 3;
    int blk = blockIdx.x;
    int b = blk >> 7, h = blk & 127;
    int p0 = blk * 128;
    int c4 = tid & 15, grp = tid >> 4;

    float dacc[4][4];
    #pragma unroll
    for (int n = 0; n < 4; n++)
        #pragma unroll
        for (int q = 0; q < 4; q++) dacc[n][q] = 0.f;

    int arow = wid*16 + ((lmat & 1) << 3) + lrow;
    uint32_t aRowOff = arow*128;
    int asw  = (arow & 7) << 4;
    int acol = (lmat >> 1) << 4;
    int browb = ((lmat >> 1) << 3) + lrow;
    int bsw  = (browb & 7) << 4;
    int bcol = (lmat & 1) << 4;

    for (int tap = 0; tap < 9; tap++) {
        __syncthreads();
        for (int i = tid; i < 256; i += 256) {
            int row = i >> 3, q = i & 7;
            int off = row*128 + ((q*16) ^ ((row & 7)*16));
            *(uint4*)(wH + off) = ((const uint4*)&g_woh[tap*2048])[i];
        }
        int y = h + tap/3 - 1;
        int dxs = tap%3 - 1;
        #pragma unroll 4
        for (int it = 0; it < 8; it++) {
            int px = it*16 + grp;
            int xx = px + dxs;
            float4 v = make_float4(0.f,0.f,0.f,0.f);
            if (y >= 0 && y < Hn && xx >= 0 && xx < Wn)
                v = *(const float4*)&g_xt[(((size_t)b*Hn + y)*Wn + xx)*Cn + c4*4];
            uint2 hi, lo; split4(v, hi, lo);
            int off = px*128 + ((c4*8) ^ ((px & 7)*16));
            *(uint2*)(aH + off) = hi;
            *(uint2*)(aL + off) = lo;
        }
        __syncthreads();
        #pragma unroll
        for (int ks = 0; ks < 4; ks++) {
            uint32_t aoff = aRowOff + ((acol + ks*32) ^ asw);
            uint32_t ah0,ah1,ah2,ah3, al0,al1,al2,al3;
            LDSM4(ah0,ah1,ah2,ah3, aHb + aoff);
            LDSM4(al0,al1,al2,al3, aLb + aoff);
            #pragma unroll
            for (int np = 0; np < 2; np++) {
                uint32_t boff = (np*16 + browb)*128 + ((bcol + ks*32) ^ bsw);
                uint32_t bh0,bh1,bh2,bh3;
                LDSM4(bh0,bh1,bh2,bh3, wHb + boff);
                MMA16816(dacc[2*np][0],dacc[2*np][1],dacc[2*np][2],dacc[2*np][3],
                         ah0,ah1,ah2,ah3, bh0,bh1);
                MMA16816(dacc[2*np][0],dacc[2*np][1],dacc[2*np][2],dacc[2*np][3],
                         al0,al1,al2,al3, bh0,bh1);
                MMA16816(dacc[2*np+1][0],dacc[2*np+1][1],dacc[2*np+1][2],dacc[2*np+1][3],
                         ah0,ah1,ah2,ah3, bh2,bh3);
                MMA16816(dacc[2*np+1][0],dacc[2*np+1][1],dacc[2*np+1][2],dacc[2*np+1][3],
                         al0,al1,al2,al3, bh2,bh3);
            }
        }
    }

    int px = p0 + wid*16 + g;
    #pragma unroll
    for (int nt = 0; nt < 4; nt++) {
        int o = nt*8 + 2*tc;
        if (o < 27) {
            float v0 = dacc[nt][0], v2 = dacc[nt][2];
            if (o < 18) { v0 += off_b[o]; v2 += off_b[o]; }
            else {
                v0 = 2.0f / (1.0f + expf(-(v0 + mod_b[o-18])));
                v2 = 2.0f / (1.0f + expf(-(v2 + mod_b[o-18])));
            }
            g_om[(size_t)px*27 + o]     = v0;
            g_om[(size_t)(px+8)*27 + o] = v2;
        }
        if (o+1 < 27) {
            float v1 = dacc[nt][1], v3 = dacc[nt][3];
            if (o+1 < 18) { v1 += off_b[o+1]; v3 += off_b[o+1]; }
            else {
                v1 = 2.0f / (1.0f + expf(-(v1 + mod_b[o+1-18])));
                v3 = 2.0f / (1.0f + expf(-(v3 + mod_b[o+1-18])));
            }
            g_om[(size_t)px*27 + o+1]     = v1;
            g_om[(size_t)(px+8)*27 + o+1] = v3;
        }
    }
}

// ---------------------------------------------------------------------------
// Deformable conv: HMMA fp16 2-term + ldmatrix + swizzle, fused BN stats.
__global__ __launch_bounds__(256) void k_deform(const float* __restrict__ bias)
{
    extern __shared__ __align__(16) char sm[];
    char* aH = sm;          char* aL = sm + D_AL;
    char* wH = sm + D_WH;
    float* psm = (float*)(sm + D_PS);
    uint32_t aHb = lds_addr(aH), aLb = lds_addr(aL);
    uint32_t wHb = lds_addr(wH);

    int tid = threadIdx.x;
    int wid = tid >> 5, lane = tid & 31;
    int g = lane >> 2, tc = lane & 3;
    int lrow = lane & 7, lmat = lane >> 3;
    int blk = blockIdx.x;
    int b = blk >> 7, h = blk & 127;
    int p0 = blk * 128;
    int c4 = tid & 15, grp = tid >> 4;

    float dacc[8][4];
    #pragma unroll
    for (int n = 0; n < 8; n++)
        #pragma unroll
        for (int q = 0; q < 4; q++) dacc[n][q] = 0.f;

    int arow = wid*16 + ((lmat & 1) << 3) + lrow;
    uint32_t aRowOff = arow*128;
    int asw  = (arow & 7) << 4;
    int acol = (lmat >> 1) << 4;
    int browb = ((lmat >> 1) << 3) + lrow;
    int bsw  = (browb & 7) << 4;
    int bcol = (lmat & 1) << 4;

    for (int tap = 0; tap < 9; tap++) {
        __syncthreads();
        // stage W (64 rows x 128B)
        for (int i = tid; i < 512; i += 256) {
            int row = i >> 3, q = i & 7;
            int off = row*128 + ((q*16) ^ ((row & 7)*16));
            *(uint4*)(wH + off) = ((const uint4*)&g_wdh[tap*4096])[i];
        }
        // bilinear params (threads 0..127, one pixel each)
        if (tid < 128) {
            const float* omp = &g_om[(size_t)(p0 + tid)*27];
            float dy = omp[tap*2], dx = omp[tap*2+1], mk = omp[18+tap];
            float py = (float)(h + tap/3 - 1) + dy;
            float px_ = (float)(tid + tap%3 - 1) + dx;
            float fy = floorf(py), fx = floorf(px_);
            float ly = py - fy,    lx = px_ - fx;
            int y0 = (int)fy, x0 = (int)fx;
            int y1 = y0 + 1,  x1 = x0 + 1;
            float vy0 = (y0 >= 0 && y0 < Hn) ? 1.f : 0.f;
            float vy1 = (y1 >= 0 && y1 < Hn) ? 1.f : 0.f;
            float vx0 = (x0 >= 0 && x0 < Wn) ? 1.f : 0.f;
            float vx1 = (x1 >= 0 && x1 < Wn) ? 1.f : 0.f;
            int iy0 = min(max(y0,0),Hn-1), iy1 = min(max(y1,0),Hn-1);
            int ix0 = min(max(x0,0),Wn-1), ix1 = min(max(x1,0),Wn-1);
            int base = (b*Hn)*Wn;
            psm[tid*8+0] = (1.f-ly)*(1.f-lx)*mk * vy0*vx0;
            psm[tid*8+1] = (1.f-ly)*lx      *mk * vy0*vx1;
            psm[tid*8+2] = ly      *(1.f-lx)*mk * vy1*vx0;
            psm[tid*8+3] = ly      *lx      *mk * vy1*vx1;
            psm[tid*8+4] = __int_as_float(((base + iy0*Wn + ix0)*Cn) >> 2);
            psm[tid*8+5] = __int_as_float(((base + iy0*Wn + ix1)*Cn) >> 2);
            psm[tid*8+6] = __int_as_float(((base + iy1*Wn + ix0)*Cn) >> 2);
            psm[tid*8+7] = __int_as_float(((base + iy1*Wn + ix1)*Cn) >> 2);
        }
        __syncthreads();
        // cooperative gather + blend + split (16 lanes/px)
        {
            const float4* P = (const float4*)g_xt;
            #pragma unroll 2
            for (int it = 0; it < 8; it++) {
                int px = it*16 + grp;
                float w00 = psm[px*8+0], w01 = psm[px*8+1];
                float w10 = psm[px*8+2], w11 = psm[px*8+3];
                int i00 = __float_as_int(psm[px*8+4]);
                int i01 = __float_as_int(psm[px*8+5]);
                int i10 = __float_as_int(psm[px*8+6]);
                int i11 = __float_as_int(psm[px*8+7]);
                float4 a = P[i00 + c4], e = P[i01 + c4];
                float4 c = P[i10 + c4], d = P[i11 + c4];
                float4 v;
                v.x = w00*a.x + w01*e.x + w10*c.x + w11*d.x;
                v.y = w00*a.y + w01*e.y + w10*c.y + w11*d.y;
                v.z = w00*a.z + w01*e.z + w10*c.z + w11*d.z;
                v.w = w00*a.w + w01*e.w + w10*c.w + w11*d.w;
                uint2 hi, lo; split4(v, hi, lo);
                int off = px*128 + ((c4*8) ^ ((px & 7)*16));
                *(uint2*)(aH + off) = hi;
                *(uint2*)(aL + off) = lo;
            }
        }
        __syncthreads();
        #pragma unroll
        for (int ks = 0; ks < 4; ks++) {
            uint32_t aoff = aRowOff + ((acol + ks*32) ^ asw);
            uint32_t ah0,ah1,ah2,ah3, al0,al1,al2,al3;
            LDSM4(ah0,ah1,ah2,ah3, aHb + aoff);
            LDSM4(al0,al1,al2,al3, aLb + aoff);
            #pragma unroll
            for (int np = 0; np < 4; np++) {
                uint32_t boff = (np*16 + browb)*128 + ((bcol + ks*32) ^ bsw);
                uint32_t bh0,bh1,bh2,bh3;
                LDSM4(bh0,bh1,bh2,bh3, wHb + boff);
                MMA16816(dacc[2*np][0],dacc[2*np][1],dacc[2*np][2],dacc[2*np][3],
                         ah0,ah1,ah2,ah3, bh0,bh1);
                MMA16816(dacc[2*np][0],dacc[2*np][1],dacc[2*np][2],dacc[2*np][3],
                         al0,al1,al2,al3, bh0,bh1);
                MMA16816(dacc[2*np+1][0],dacc[2*np+1][1],dacc[2*np+1][2],dacc[2*np+1][3],
                         ah0,ah1,ah2,ah3, bh2,bh3);
                MMA16816(dacc[2*np+1][0],dacc[2*np+1][1],dacc[2*np+1][2],dacc[2*np+1][3],
                         al0,al1,al2,al3, bh2,bh3);
            }
        }
    }

    // epilogue: +bias, store y, fused BN stats
    __syncthreads();
    if (tid < 128) psm[tid] = 0.f;
    __syncthreads();

    int px = p0 + wid*16 + g;
    float ss[8], sh[8], qs[8], qh[8];
    #pragma unroll
    for (int nt = 0; nt < 8; nt++) {
        int o = nt*8 + 2*tc;
        float b0 = bias[o], b1 = bias[o+1];
        float v00 = dacc[nt][0] + b0, v01 = dacc[nt][1] + b1;
        float v10 = dacc[nt][2] + b0, v11 = dacc[nt][3] + b1;
        *(float2*)&g_y[(size_t)px*64 + o]     = make_float2(v00, v01);
        *(float2*)&g_y[(size_t)(px+8)*64 + o] = make_float2(v10, v11);
        ss[nt] = v00 + v10;        sh[nt] = v01 + v11;
        qs[nt] = v00*v00 + v10*v10; qh[nt] = v01*v01 + v11*v11;
    }
    #pragma unroll
    for (int d = 4; d < 32; d <<= 1) {
        #pragma unroll
        for (int nt = 0; nt < 8; nt++) {
            ss[nt] += __shfl_xor_sync(0xffffffffu, ss[nt], d);
            sh[nt] += __shfl_xor_sync(0xffffffffu, sh[nt], d);
            qs[nt] += __shfl_xor_sync(0xffffffffu, qs[nt], d);
            qh[nt] += __shfl_xor_sync(0xffffffffu, qh[nt], d);
        }
    }
    if (lane < 4) {
        #pragma unroll
        for (int nt = 0; nt < 8; nt++) {
            int o = nt*8 + 2*tc;
            atomicAdd(&psm[o],       ss[nt]);
            atomicAdd(&psm[o+1],     sh[nt]);
            atomicAdd(&psm[64+o],    qs[nt]);
            atomicAdd(&psm[64+o+1],  qh[nt]);
        }
    }
    __syncthreads();
    if (tid < 64) {
        atomicAdd(&g_sum[tid], psm[tid]);
        atomicAdd(&g_sq [tid], psm[64+tid]);
    }
}

// ---------------------------------------------------------------------------
__global__ __launch_bounds__(1024) void k_norm_out(
    const float* __restrict__ gamma, const float* __restrict__ beta,
    float* __restrict__ out)
{
    __shared__ float t[32][33];
    int w0 = blockIdx.x * 32, c0 = blockIdx.y * 32;
    int bh = blockIdx.z;
    int b = bh / Hn, h = bh % Hn;
    int tx = threadIdx.x, ty = threadIdx.y;

    int c = c0 + tx;
    const float inv = 1.0f / (float)PIX;
    float mean = g_sum[c] * inv;
    float var  = g_sq[c] * inv - mean*mean;
    float rstd = rsqrtf(var + 1e-5f);
    float sc = gamma[c] * rstd;
    float sh = beta[c] - mean * sc;

    float v = g_y[((size_t)bh*Wn + (w0+ty))*Cn + c];
    t[ty][tx] = fmaxf(v*sc + sh, 0.f);
    __syncthreads();
    out[(((size_t)b*Cn + (c0+ty))*Hn + h)*Wn + (w0+tx)] = t[tx][ty];
}

// ---------------------------------------------------------------------------
extern "C" void kernel_launch(void* const* d_in, const int* in_sizes, int n_in,
                              void* d_out, int out_size)
{
    const float* x     = (const float*)d_in[0];
    const float* off_w = (const float*)d_in[1];
    const float* off_b = (const float*)d_in[2];
    const float* mod_w = (const float*)d_in[3];
    const float* mod_b = (const float*)d_in[4];
    const float* wmat  = (const float*)d_in[5];
    const float* bias  = (const float*)d_in[6];
    const float* gamma = (const float*)d_in[7];
    const float* beta  = (const float*)d_in[8];
    float* out = (float*)d_out;

    static int configured = 0;
    if (!configured) {
        cudaFuncSetAttribute(k_offmask, cudaFuncAttributeMaxDynamicSharedMemorySize, OSM);
        cudaFuncSetAttribute(k_deform,  cudaFuncAttributeMaxDynamicSharedMemorySize, DSM);
        configured = 1;
    }

    dim3 tgrid(Wn/32, Cn/32, Bn*Hn);
    dim3 tblk(32, 32);

    k_zero<<<1, 64>>>();
    k_wprep<<<64, 256>>>(wmat, off_w, mod_w);
    k_transpose_in<<<tgrid, tblk>>>(x);
    k_offmask<<<PIX/128, 256, OSM>>>(off_b, mod_b);
    k_deform <<<PIX/128, 256, DSM>>>(bias);
    k_norm_out<<<tgrid, tblk>>>(gamma, beta, out);
}

// round 13
// speedup vs baseline: 1.7322x; 1.3321x over previous
#include <cuda_runtime.h>
#include <cuda_fp16.h>
#include <math.h>
#include <cstdint>

#define Bn   8
#define Cn   64
#define Hn   128
#define Wn   128
#define PIX  (Bn*Hn*Wn)    // 131072

// offmask smem: aH 16384 | wH 4096
#define O_WH 16384
#define OSM  20480
// deform smem: aH 16384 | wH 8192 | psm 4096
#define D_WH 16384
#define D_PS 24576
#define DSM  28672

// Scratch
__device__ __half g_x16[PIX*Cn];          // x channels-last fp16 (16.7MB)
__device__ float g_om[PIX*27];            // offsets+mask per pixel
__device__ float g_y [PIX*Cn];            // deform out [pix][c]
__device__ __half g_wdh[9*64*64];         // deform W fp16  [tap][o][c]
__device__ __half g_woh[9*32*64];         // offmask W fp16 [tap][o(32)][c]
__device__ float g_sum[Cn];
__device__ float g_sq [Cn];

#define MMA16816(d0,d1,d2,d3,a0,a1,a2,a3,b0,b1) \
    asm volatile("mma.sync.aligned.m16n8k16.row.col.f32.f16.f16.f32 " \
        "{%0,%1,%2,%3}, {%4,%5,%6,%7}, {%8,%9}, {%0,%1,%2,%3};" \
        : "+f"(d0), "+f"(d1), "+f"(d2), "+f"(d3) \
        : "r"(a0), "r"(a1), "r"(a2), "r"(a3), "r"(b0), "r"(b1))

#define LDSM4(r0,r1,r2,r3,a) \
    asm volatile("ldmatrix.sync.aligned.m8n8.x4.shared.b16 {%0,%1,%2,%3}, [%4];" \
        : "=r"(r0), "=r"(r1), "=r"(r2), "=r"(r3) : "r"(a))

__device__ __forceinline__ uint32_t lds_addr(const void* p) {
    return (uint32_t)__cvta_generic_to_shared(p);
}

// ---------------------------------------------------------------------------
__global__ void k_zero() {
    int i = threadIdx.x;
    if (i < Cn) { g_sum[i] = 0.f; g_sq[i] = 0.f; }
}

// ---------------------------------------------------------------------------
__global__ __launch_bounds__(256) void k_wprep(
    const float* __restrict__ wmat,
    const float* __restrict__ off_w, const float* __restrict__ mod_w)
{
    for (int i = blockIdx.x*256 + threadIdx.x; i < 9*4096 + 9*2048; i += gridDim.x*256) {
        if (i < 9*4096) {
            int tap = i >> 12, r = i & 4095;
            int o = r >> 6, c = r & 63;
            g_wdh[i] = __float2half_rn(wmat[(o*64 + c)*9 + tap]);
        } else {
            int j = i - 9*4096;
            int tap = j >> 11, r = j & 2047;
            int o = r >> 6, c = r & 63;
            float v = 0.f;
            if (o < 18)      v = off_w[(o*64 + c)*9 + tap];
            else if (o < 27) v = mod_w[((o-18)*64 + c)*9 + tap];
            g_woh[j] = __float2half_rn(v);
        }
    }
}

// ---------------------------------------------------------------------------
// x[b][c][h][w] (fp32) -> g_x16[((b*H+h)*W+w)*C + c] (fp16)
__global__ __launch_bounds__(1024) void k_transpose_in(const float* __restrict__ x) {
    __shared__ float t[32][33];
    int w0 = blockIdx.x * 32, c0 = blockIdx.y * 32;
    int bh = blockIdx.z;
    int b = bh / Hn, h = bh % Hn;
    int tx = threadIdx.x, ty = threadIdx.y;
    t[ty][tx] = x[(((b*Cn) + (c0+ty))*Hn + h)*Wn + (w0+tx)];
    __syncthreads();
    g_x16[((size_t)bh*Wn + (w0+ty))*Cn + (c0+tx)] = __float2half_rn(t[tx][ty]);
}

// ---------------------------------------------------------------------------
// offset/mask conv: fp16 HMMA (single term) + ldmatrix + XOR swizzle, 256 thr.
__global__ __launch_bounds__(256) void k_offmask(
    const float* __restrict__ off_b, const float* __restrict__ mod_b)
{
    extern __shared__ __align__(16) char sm[];
    char* aH = sm;
    char* wH = sm + O_WH;
    uint32_t aHb = lds_addr(aH), wHb = lds_addr(wH);

    int tid = threadIdx.x;
    int wid = tid >> 5, lane = tid & 31;
    int g = lane >> 2, tc = lane & 3;
    int lrow = lane & 7, lmat = lane >> 3;
    int blk = blockIdx.x;
    int b = blk >> 7, h = blk & 127;
    int p0 = blk * 128;
    int c4 = tid & 15, grp = tid >> 4;

    float dacc[4][4];
    #pragma unroll
    for (int n = 0; n < 4; n++)
        #pragma unroll
        for (int q = 0; q < 4; q++) dacc[n][q] = 0.f;

    int arow = wid*16 + ((lmat & 1) << 3) + lrow;
    uint32_t aRowOff = arow*128;
    int asw  = (arow & 7) << 4;
    int acol = (lmat >> 1) << 4;
    int browb = ((lmat >> 1) << 3) + lrow;
    int bsw  = (browb & 7) << 4;
    int bcol = (lmat & 1) << 4;

    for (int tap = 0; tap < 9; tap++) {
        __syncthreads();
        // stage W (32 rows x 128B)
        for (int i = tid; i < 256; i += 256) {
            int row = i >> 3, q = i & 7;
            int off = row*128 + ((q*16) ^ ((row & 7)*16));
            *(uint4*)(wH + off) = ((const uint4*)&g_woh[tap*2048])[i];
        }
        // stage A: shifted fp16 x row (straight copy)
        int y = h + tap/3 - 1;
        int dxs = tap%3 - 1;
        #pragma unroll 4
        for (int it = 0; it < 8; it++) {
            int px = it*16 + grp;
            int xx = px + dxs;
            uint2 v = make_uint2(0u, 0u);
            if (y >= 0 && y < Hn && xx >= 0 && xx < Wn)
                v = *(const uint2*)&g_x16[(((size_t)b*Hn + y)*Wn + xx)*Cn + c4*4];
            int off = px*128 + ((c4*8) ^ ((px & 7)*16));
            *(uint2*)(aH + off) = v;
        }
        __syncthreads();
        #pragma unroll
        for (int ks = 0; ks < 4; ks++) {
            uint32_t aoff = aRowOff + ((acol + ks*32) ^ asw);
            uint32_t ah0,ah1,ah2,ah3;
            LDSM4(ah0,ah1,ah2,ah3, aHb + aoff);
            #pragma unroll
            for (int np = 0; np < 2; np++) {
                uint32_t boff = (np*16 + browb)*128 + ((bcol + ks*32) ^ bsw);
                uint32_t bh0,bh1,bh2,bh3;
                LDSM4(bh0,bh1,bh2,bh3, wHb + boff);
                MMA16816(dacc[2*np][0],dacc[2*np][1],dacc[2*np][2],dacc[2*np][3],
                         ah0,ah1,ah2,ah3, bh0,bh1);
                MMA16816(dacc[2*np+1][0],dacc[2*np+1][1],dacc[2*np+1][2],dacc[2*np+1][3],
                         ah0,ah1,ah2,ah3, bh2,bh3);
            }
        }
    }

    int px = p0 + wid*16 + g;
    #pragma unroll
    for (int nt = 0; nt < 4; nt++) {
        int o = nt*8 + 2*tc;
        if (o < 27) {
            float v0 = dacc[nt][0], v2 = dacc[nt][2];
            if (o < 18) { v0 += off_b[o]; v2 += off_b[o]; }
            else {
                v0 = 2.0f / (1.0f + expf(-(v0 + mod_b[o-18])));
                v2 = 2.0f / (1.0f + expf(-(v2 + mod_b[o-18])));
            }
            g_om[(size_t)px*27 + o]     = v0;
            g_om[(size_t)(px+8)*27 + o] = v2;
        }
        if (o+1 < 27) {
            float v1 = dacc[nt][1], v3 = dacc[nt][3];
            if (o+1 < 18) { v1 += off_b[o+1]; v3 += off_b[o+1]; }
            else {
                v1 = 2.0f / (1.0f + expf(-(v1 + mod_b[o+1-18])));
                v3 = 2.0f / (1.0f + expf(-(v3 + mod_b[o+1-18])));
            }
            g_om[(size_t)px*27 + o+1]     = v1;
            g_om[(size_t)(px+8)*27 + o+1] = v3;
        }
    }
}

// ---------------------------------------------------------------------------
// Deformable conv: fp16 gather + fp32 blend + fp16 HMMA (single term).
__global__ __launch_bounds__(256) void k_deform(const float* __restrict__ bias)
{
    extern __shared__ __align__(16) char sm[];
    char* aH = sm;
    char* wH = sm + D_WH;
    float* psm = (float*)(sm + D_PS);
    uint32_t aHb = lds_addr(aH), wHb = lds_addr(wH);

    int tid = threadIdx.x;
    int wid = tid >> 5, lane = tid & 31;
    int g = lane >> 2, tc = lane & 3;
    int lrow = lane & 7, lmat = lane >> 3;
    int blk = blockIdx.x;
    int b = blk >> 7, h = blk & 127;
    int p0 = blk * 128;
    int c4 = tid & 15, grp = tid >> 4;

    float dacc[8][4];
    #pragma unroll
    for (int n = 0; n < 8; n++)
        #pragma unroll
        for (int q = 0; q < 4; q++) dacc[n][q] = 0.f;

    int arow = wid*16 + ((lmat & 1) << 3) + lrow;
    uint32_t aRowOff = arow*128;
    int asw  = (arow & 7) << 4;
    int acol = (lmat >> 1) << 4;
    int browb = ((lmat >> 1) << 3) + lrow;
    int bsw  = (browb & 7) << 4;
    int bcol = (lmat & 1) << 4;

    for (int tap = 0; tap < 9; tap++) {
        __syncthreads();
        // stage W (64 rows x 128B)
        for (int i = tid; i < 512; i += 256) {
            int row = i >> 3, q = i & 7;
            int off = row*128 + ((q*16) ^ ((row & 7)*16));
            *(uint4*)(wH + off) = ((const uint4*)&g_wdh[tap*4096])[i];
        }
        // bilinear params (threads 0..127, one pixel each)
        if (tid < 128) {
            const float* omp = &g_om[(size_t)(p0 + tid)*27];
            float dy = omp[tap*2], dx = omp[tap*2+1], mk = omp[18+tap];
            float py = (float)(h + tap/3 - 1) + dy;
            float px_ = (float)(tid + tap%3 - 1) + dx;
            float fy = floorf(py), fx = floorf(px_);
            float ly = py - fy,    lx = px_ - fx;
            int y0 = (int)fy, x0 = (int)fx;
            int y1 = y0 + 1,  x1 = x0 + 1;
            float vy0 = (y0 >= 0 && y0 < Hn) ? 1.f : 0.f;
            float vy1 = (y1 >= 0 && y1 < Hn) ? 1.f : 0.f;
            float vx0 = (x0 >= 0 && x0 < Wn) ? 1.f : 0.f;
            float vx1 = (x1 >= 0 && x1 < Wn) ? 1.f : 0.f;
            int iy0 = min(max(y0,0),Hn-1), iy1 = min(max(y1,0),Hn-1);
            int ix0 = min(max(x0,0),Wn-1), ix1 = min(max(x1,0),Wn-1);
            int base = (b*Hn)*Wn;
            psm[tid*8+0] = (1.f-ly)*(1.f-lx)*mk * vy0*vx0;
            psm[tid*8+1] = (1.f-ly)*lx      *mk * vy0*vx1;
            psm[tid*8+2] = ly      *(1.f-lx)*mk * vy1*vx0;
            psm[tid*8+3] = ly      *lx      *mk * vy1*vx1;
            psm[tid*8+4] = __int_as_float(base + iy0*Wn + ix0);
            psm[tid*8+5] = __int_as_float(base + iy0*Wn + ix1);
            psm[tid*8+6] = __int_as_float(base + iy1*Wn + ix0);
            psm[tid*8+7] = __int_as_float(base + iy1*Wn + ix1);
        }
        __syncthreads();
        // cooperative gather (fp16 corners) + fp32 blend + fp16 store
        {
            #pragma unroll 2
            for (int it = 0; it < 8; it++) {
                int px = it*16 + grp;
                float w00 = psm[px*8+0], w01 = psm[px*8+1];
                float w10 = psm[px*8+2], w11 = psm[px*8+3];
                int i00 = __float_as_int(psm[px*8+4]);
                int i01 = __float_as_int(psm[px*8+5]);
                int i10 = __float_as_int(psm[px*8+6]);
                int i11 = __float_as_int(psm[px*8+7]);
                uint2 ua = *(const uint2*)&g_x16[(size_t)i00*Cn + c4*4];
                uint2 ue = *(const uint2*)&g_x16[(size_t)i01*Cn + c4*4];
                uint2 uc = *(const uint2*)&g_x16[(size_t)i10*Cn + c4*4];
                uint2 ud = *(const uint2*)&g_x16[(size_t)i11*Cn + c4*4];
                float2 a0 = __half22float2(*(__half2*)&ua.x), a1 = __half22float2(*(__half2*)&ua.y);
                float2 e0 = __half22float2(*(__half2*)&ue.x), e1 = __half22float2(*(__half2*)&ue.y);
                float2 q0 = __half22float2(*(__half2*)&uc.x), q1 = __half22float2(*(__half2*)&uc.y);
                float2 d0 = __half22float2(*(__half2*)&ud.x), d1 = __half22float2(*(__half2*)&ud.y);
                float2 v0, v1;
                v0.x = w00*a0.x + w01*e0.x + w10*q0.x + w11*d0.x;
                v0.y = w00*a0.y + w01*e0.y + w10*q0.y + w11*d0.y;
                v1.x = w00*a1.x + w01*e1.x + w10*q1.x + w11*d1.x;
                v1.y = w00*a1.y + w01*e1.y + w10*q1.y + w11*d1.y;
                __half2 r0 = __float22half2_rn(v0);
                __half2 r1 = __float22half2_rn(v1);
                uint2 outv;
                outv.x = *(uint32_t*)&r0;
                outv.y = *(uint32_t*)&r1;
                int off = px*128 + ((c4*8) ^ ((px & 7)*16));
                *(uint2*)(aH + off) = outv;
            }
        }
        __syncthreads();
        #pragma unroll
        for (int ks = 0; ks < 4; ks++) {
            uint32_t aoff = aRowOff + ((acol + ks*32) ^ asw);
            uint32_t ah0,ah1,ah2,ah3;
            LDSM4(ah0,ah1,ah2,ah3, aHb + aoff);
            #pragma unroll
            for (int np = 0; np < 4; np++) {
                uint32_t boff = (np*16 + browb)*128 + ((bcol + ks*32) ^ bsw);
                uint32_t bh0,bh1,bh2,bh3;
                LDSM4(bh0,bh1,bh2,bh3, wHb + boff);
                MMA16816(dacc[2*np][0],dacc[2*np][1],dacc[2*np][2],dacc[2*np][3],
                         ah0,ah1,ah2,ah3, bh0,bh1);
                MMA16816(dacc[2*np+1][0],dacc[2*np+1][1],dacc[2*np+1][2],dacc[2*np+1][3],
                         ah0,ah1,ah2,ah3, bh2,bh3);
            }
        }
    }

    // epilogue: +bias, store y, fused BN stats
    __syncthreads();
    if (tid < 128) psm[tid] = 0.f;
    __syncthreads();

    int px = p0 + wid*16 + g;
    float ss[8], sh[8], qs[8], qh[8];
    #pragma unroll
    for (int nt = 0; nt < 8; nt++) {
        int o = nt*8 + 2*tc;
        float b0 = bias[o], b1 = bias[o+1];
        float v00 = dacc[nt][0] + b0, v01 = dacc[nt][1] + b1;
        float v10 = dacc[nt][2] + b0, v11 = dacc[nt][3] + b1;
        *(float2*)&g_y[(size_t)px*64 + o]     = make_float2(v00, v01);
        *(float2*)&g_y[(size_t)(px+8)*64 + o] = make_float2(v10, v11);
        ss[nt] = v00 + v10;        sh[nt] = v01 + v11;
        qs[nt] = v00*v00 + v10*v10; qh[nt] = v01*v01 + v11*v11;
    }
    #pragma unroll
    for (int d = 4; d < 32; d <<= 1) {
        #pragma unroll
        for (int nt = 0; nt < 8; nt++) {
            ss[nt] += __shfl_xor_sync(0xffffffffu, ss[nt], d);
            sh[nt] += __shfl_xor_sync(0xffffffffu, sh[nt], d);
            qs[nt] += __shfl_xor_sync(0xffffffffu, qs[nt], d);
            qh[nt] += __shfl_xor_sync(0xffffffffu, qh[nt], d);
        }
    }
    if (lane < 4) {
        #pragma unroll
        for (int nt = 0; nt < 8; nt++) {
            int o = nt*8 + 2*tc;
            atomicAdd(&psm[o],       ss[nt]);
            atomicAdd(&psm[o+1],     sh[nt]);
            atomicAdd(&psm[64+o],    qs[nt]);
            atomicAdd(&psm[64+o+1],  qh[nt]);
        }
    }
    __syncthreads();
    if (tid < 64) {
        atomicAdd(&g_sum[tid], psm[tid]);
        atomicAdd(&g_sq [tid], psm[64+tid]);
    }
}

// ---------------------------------------------------------------------------
__global__ __launch_bounds__(1024) void k_norm_out(
    const float* __restrict__ gamma, const float* __restrict__ beta,
    float* __restrict__ out)
{
    __shared__ float t[32][33];
    int w0 = blockIdx.x * 32, c0 = blockIdx.y * 32;
    int bh = blockIdx.z;
    int b = bh / Hn, h = bh % Hn;
    int tx = threadIdx.x, ty = threadIdx.y;

    int c = c0 + tx;
    const float inv = 1.0f / (float)PIX;
    float mean = g_sum[c] * inv;
    float var  = g_sq[c] * inv - mean*mean;
    float rstd = rsqrtf(var + 1e-5f);
    float sc = gamma[c] * rstd;
    float sh = beta[c] - mean * sc;

    float v = g_y[((size_t)bh*Wn + (w0+ty))*Cn + c];
    t[ty][tx] = fmaxf(v*sc + sh, 0.f);
    __syncthreads();
    out[(((size_t)b*Cn + (c0+ty))*Hn + h)*Wn + (w0+tx)] = t[tx][ty];
}

// ---------------------------------------------------------------------------
extern "C" void kernel_launch(void* const* d_in, const int* in_sizes, int n_in,
                              void* d_out, int out_size)
{
    const float* x     = (const float*)d_in[0];
    const float* off_w = (const float*)d_in[1];
    const float* off_b = (const float*)d_in[2];
    const float* mod_w = (const float*)d_in[3];
    const float* mod_b = (const float*)d_in[4];
    const float* wmat  = (const float*)d_in[5];
    const float* bias  = (const float*)d_in[6];
    const float* gamma = (const float*)d_in[7];
    const float* beta  = (const float*)d_in[8];
    float* out = (float*)d_out;

    static int configured = 0;
    if (!configured) {
        cudaFuncSetAttribute(k_offmask, cudaFuncAttributeMaxDynamicSharedMemorySize, OSM);
        cudaFuncSetAttribute(k_deform,  cudaFuncAttributeMaxDynamicSharedMemorySize, DSM);
        configured = 1;
    }

    dim3 tgrid(Wn/32, Cn/32, Bn*Hn);
    dim3 tblk(32, 32);

    k_zero<<<1, 64>>>();
    k_wprep<<<64, 256>>>(wmat, off_w, mod_w);
    k_transpose_in<<<tgrid, tblk>>>(x);
    k_offmask<<<PIX/128, 256, OSM>>>(off_b, mod_b);
    k_deform <<<PIX/128, 256, DSM>>>(bias);
    k_norm_out<<<tgrid, tblk>>>(gamma, beta, out);
}

// round 14
// speedup vs baseline: 1.8396x; 1.0620x over previous
#include <cuda_runtime.h>
#include <cuda_fp16.h>
#include <math.h>
#include <cstdint>

#define Bn   8
#define Cn   64
#define Hn   128
#define Wn   128
#define PIX  (Bn*Hn*Wn)    // 131072

// fused conv smem (bytes): aH 16384 | wH 8192 | om 14336 | psm 4096
#define F_WH 16384
#define F_OM 24576
#define F_PS 38912
#define FSM  43008

// Scratch
__device__ __half g_x16[PIX*Cn];          // x channels-last fp16 (16.7MB)
__device__ float g_y [PIX*Cn];            // deform out [pix][c]
__device__ __half g_wdh[9*64*64];         // deform W fp16  [tap][o][c]
__device__ __half g_woh[9*32*64];         // offmask W fp16 [tap][o(32)][c]
__device__ float g_sum[Cn];
__device__ float g_sq [Cn];

#define MMA16816(d0,d1,d2,d3,a0,a1,a2,a3,b0,b1) \
    asm volatile("mma.sync.aligned.m16n8k16.row.col.f32.f16.f16.f32 " \
        "{%0,%1,%2,%3}, {%4,%5,%6,%7}, {%8,%9}, {%0,%1,%2,%3};" \
        : "+f"(d0), "+f"(d1), "+f"(d2), "+f"(d3) \
        : "r"(a0), "r"(a1), "r"(a2), "r"(a3), "r"(b0), "r"(b1))

#define LDSM4(r0,r1,r2,r3,a) \
    asm volatile("ldmatrix.sync.aligned.m8n8.x4.shared.b16 {%0,%1,%2,%3}, [%4];" \
        : "=r"(r0), "=r"(r1), "=r"(r2), "=r"(r3) : "r"(a))

__device__ __forceinline__ uint32_t lds_addr(const void* p) {
    return (uint32_t)__cvta_generic_to_shared(p);
}

// ---------------------------------------------------------------------------
__global__ void k_zero() {
    int i = threadIdx.x;
    if (i < Cn) { g_sum[i] = 0.f; g_sq[i] = 0.f; }
}

// ---------------------------------------------------------------------------
__global__ __launch_bounds__(256) void k_wprep(
    const float* __restrict__ wmat,
    const float* __restrict__ off_w, const float* __restrict__ mod_w)
{
    for (int i = blockIdx.x*256 + threadIdx.x; i < 9*4096 + 9*2048; i += gridDim.x*256) {
        if (i < 9*4096) {
            int tap = i >> 12, r = i & 4095;
            int o = r >> 6, c = r & 63;
            g_wdh[i] = __float2half_rn(wmat[(o*64 + c)*9 + tap]);
        } else {
            int j = i - 9*4096;
            int tap = j >> 11, r = j & 2047;
            int o = r >> 6, c = r & 63;
            float v = 0.f;
            if (o < 18)      v = off_w[(o*64 + c)*9 + tap];
            else if (o < 27) v = mod_w[((o-18)*64 + c)*9 + tap];
            g_woh[j] = __float2half_rn(v);
        }
    }
}

// ---------------------------------------------------------------------------
// x[b][c][h][w] (fp32) -> g_x16[((b*H+h)*W+w)*C + c] (fp16)
__global__ __launch_bounds__(1024) void k_transpose_in(const float* __restrict__ x) {
    __shared__ float t[32][33];
    int w0 = blockIdx.x * 32, c0 = blockIdx.y * 32;
    int bh = blockIdx.z;
    int b = bh / Hn, h = bh % Hn;
    int tx = threadIdx.x, ty = threadIdx.y;
    t[ty][tx] = x[(((b*Cn) + (c0+ty))*Hn + h)*Wn + (w0+tx)];
    __syncthreads();
    g_x16[((size_t)bh*Wn + (w0+ty))*Cn + (c0+tx)] = __float2half_rn(t[tx][ty]);
}

// ---------------------------------------------------------------------------
// FUSED offset/mask conv + deformable conv. Block = 1 row (128 px), 256 thr.
// Phase 1: offmask GEMM -> om in SMEM. Phase 2: deform GEMM (gather via om).
__global__ __launch_bounds__(256) void k_conv(
    const float* __restrict__ off_b, const float* __restrict__ mod_b,
    const float* __restrict__ bias)
{
    extern __shared__ __align__(16) char sm[];
    char* aH = sm;
    char* wH = sm + F_WH;
    float* om = (float*)(sm + F_OM);     // [128][28]
    float* psm = (float*)(sm + F_PS);    // [128][8]
    uint32_t aHb = lds_addr(aH), wHb = lds_addr(wH);

    int tid = threadIdx.x;
    int wid = tid >> 5, lane = tid & 31;
    int g = lane >> 2, tc = lane & 3;
    int lrow = lane & 7, lmat = lane >> 3;
    int blk = blockIdx.x;
    int b = blk >> 7, h = blk & 127;
    int p0 = blk * 128;
    int c8 = tid & 7, grp8 = tid >> 3;   // 16B lanes: 8 lanes/px, 32 px groups

    // common fragment addressing
    int arow = wid*16 + ((lmat & 1) << 3) + lrow;
    uint32_t aRowOff = arow*128;
    int asw  = (arow & 7) << 4;
    int acol = (lmat >> 1) << 4;
    int browb = ((lmat >> 1) << 3) + lrow;
    int bsw  = (browb & 7) << 4;
    int bcol = (lmat & 1) << 4;

    // ============================ PHASE 1: offmask =========================
    {
        float dacc[4][4];
        #pragma unroll
        for (int n = 0; n < 4; n++)
            #pragma unroll
            for (int q = 0; q < 4; q++) dacc[n][q] = 0.f;

        for (int tap = 0; tap < 9; tap++) {
            __syncthreads();
            // stage W (32 rows x 128B)
            for (int i = tid; i < 256; i += 256) {
                int row = i >> 3, q = i & 7;
                int off = row*128 + ((q*16) ^ ((row & 7)*16));
                *(uint4*)(wH + off) = ((const uint4*)&g_woh[tap*2048])[i];
            }
            // stage A: shifted fp16 x row, 16B lanes
            int y = h + tap/3 - 1;
            int dxs = tap%3 - 1;
            #pragma unroll
            for (int it = 0; it < 4; it++) {
                int px = it*32 + grp8;
                int xx = px + dxs;
                uint4 v = make_uint4(0u,0u,0u,0u);
                if (y >= 0 && y < Hn && xx >= 0 && xx < Wn)
                    v = *(const uint4*)&g_x16[(((size_t)b*Hn + y)*Wn + xx)*Cn + c8*8];
                int off = px*128 + ((c8*16) ^ ((px & 7)*16));
                *(uint4*)(aH + off) = v;
            }
            __syncthreads();
            #pragma unroll
            for (int ks = 0; ks < 4; ks++) {
                uint32_t aoff = aRowOff + ((acol + ks*32) ^ asw);
                uint32_t ah0,ah1,ah2,ah3;
                LDSM4(ah0,ah1,ah2,ah3, aHb + aoff);
                #pragma unroll
                for (int np = 0; np < 2; np++) {
                    uint32_t boff = (np*16 + browb)*128 + ((bcol + ks*32) ^ bsw);
                    uint32_t bh0,bh1,bh2,bh3;
                    LDSM4(bh0,bh1,bh2,bh3, wHb + boff);
                    MMA16816(dacc[2*np][0],dacc[2*np][1],dacc[2*np][2],dacc[2*np][3],
                             ah0,ah1,ah2,ah3, bh0,bh1);
                    MMA16816(dacc[2*np+1][0],dacc[2*np+1][1],dacc[2*np+1][2],dacc[2*np+1][3],
                             ah0,ah1,ah2,ah3, bh2,bh3);
                }
            }
        }
        // epilogue -> om smem
        __syncthreads();
        int lpx = wid*16 + g;
        #pragma unroll
        for (int nt = 0; nt < 4; nt++) {
            int o = nt*8 + 2*tc;
            #pragma unroll
            for (int j = 0; j < 2; j++) {
                int oo = o + j;
                if (oo >= 27) continue;
                float v0 = dacc[nt][j], v1 = dacc[nt][2+j];
                if (oo < 18) { float bv = off_b[oo]; v0 += bv; v1 += bv; }
                else {
                    float bv = mod_b[oo-18];
                    v0 = 2.0f / (1.0f + expf(-(v0 + bv)));
                    v1 = 2.0f / (1.0f + expf(-(v1 + bv)));
                }
                om[lpx*28 + oo]     = v0;
                om[(lpx+8)*28 + oo] = v1;
            }
        }
    }

    // ============================ PHASE 2: deform ==========================
    float dacc[8][4];
    #pragma unroll
    for (int n = 0; n < 8; n++)
        #pragma unroll
        for (int q = 0; q < 4; q++) dacc[n][q] = 0.f;

    for (int tap = 0; tap < 9; tap++) {
        __syncthreads();
        // stage W (64 rows x 128B)
        for (int i = tid; i < 512; i += 256) {
            int row = i >> 3, q = i & 7;
            int off = row*128 + ((q*16) ^ ((row & 7)*16));
            *(uint4*)(wH + off) = ((const uint4*)&g_wdh[tap*4096])[i];
        }
        // bilinear params (threads 0..127, one pixel each; om from SMEM)
        if (tid < 128) {
            const float* omp = &om[tid*28];
            float dy = omp[tap*2], dx = omp[tap*2+1], mk = omp[18+tap];
            float py = (float)(h + tap/3 - 1) + dy;
            float px_ = (float)(tid + tap%3 - 1) + dx;
            float fy = floorf(py), fx = floorf(px_);
            float ly = py - fy,    lx = px_ - fx;
            int y0 = (int)fy, x0 = (int)fx;
            int y1 = y0 + 1,  x1 = x0 + 1;
            float vy0 = (y0 >= 0 && y0 < Hn) ? 1.f : 0.f;
            float vy1 = (y1 >= 0 && y1 < Hn) ? 1.f : 0.f;
            float vx0 = (x0 >= 0 && x0 < Wn) ? 1.f : 0.f;
            float vx1 = (x1 >= 0 && x1 < Wn) ? 1.f : 0.f;
            int iy0 = min(max(y0,0),Hn-1), iy1 = min(max(y1,0),Hn-1);
            int ix0 = min(max(x0,0),Wn-1), ix1 = min(max(x1,0),Wn-1);
            int base = (b*Hn)*Wn;
            psm[tid*8+0] = (1.f-ly)*(1.f-lx)*mk * vy0*vx0;
            psm[tid*8+1] = (1.f-ly)*lx      *mk * vy0*vx1;
            psm[tid*8+2] = ly      *(1.f-lx)*mk * vy1*vx0;
            psm[tid*8+3] = ly      *lx      *mk * vy1*vx1;
            psm[tid*8+4] = __int_as_float(base + iy0*Wn + ix0);
            psm[tid*8+5] = __int_as_float(base + iy0*Wn + ix1);
            psm[tid*8+6] = __int_as_float(base + iy1*Wn + ix0);
            psm[tid*8+7] = __int_as_float(base + iy1*Wn + ix1);
        }
        __syncthreads();
        // gather (16B lanes: 8 lanes/px) + fp32 blend + fp16 store
        #pragma unroll
        for (int it = 0; it < 4; it++) {
            int px = it*32 + grp8;
            float w00 = psm[px*8+0], w01 = psm[px*8+1];
            float w10 = psm[px*8+2], w11 = psm[px*8+3];
            int i00 = __float_as_int(psm[px*8+4]);
            int i01 = __float_as_int(psm[px*8+5]);
            int i10 = __float_as_int(psm[px*8+6]);
            int i11 = __float_as_int(psm[px*8+7]);
            uint4 ua = *(const uint4*)&g_x16[(size_t)i00*Cn + c8*8];
            uint4 ue = *(const uint4*)&g_x16[(size_t)i01*Cn + c8*8];
            uint4 uc = *(const uint4*)&g_x16[(size_t)i10*Cn + c8*8];
            uint4 ud = *(const uint4*)&g_x16[(size_t)i11*Cn + c8*8];
            uint4 outv;
            const uint32_t* pa = &ua.x;
            const uint32_t* pe = &ue.x;
            const uint32_t* pc = &uc.x;
            const uint32_t* pd = &ud.x;
            uint32_t* po = &outv.x;
            #pragma unroll
            for (int j = 0; j < 4; j++) {
                float2 av = __half22float2(*(const __half2*)&pa[j]);
                float2 ev = __half22float2(*(const __half2*)&pe[j]);
                float2 cv = __half22float2(*(const __half2*)&pc[j]);
                float2 dv = __half22float2(*(const __half2*)&pd[j]);
                float2 v;
                v.x = w00*av.x + w01*ev.x + w10*cv.x + w11*dv.x;
                v.y = w00*av.y + w01*ev.y + w10*cv.y + w11*dv.y;
                __half2 r = __float22half2_rn(v);
                po[j] = *(const uint32_t*)&r;
            }
            int off = px*128 + ((c8*16) ^ ((px & 7)*16));
            *(uint4*)(aH + off) = outv;
        }
        __syncthreads();
        #pragma unroll
        for (int ks = 0; ks < 4; ks++) {
            uint32_t aoff = aRowOff + ((acol + ks*32) ^ asw);
            uint32_t ah0,ah1,ah2,ah3;
            LDSM4(ah0,ah1,ah2,ah3, aHb + aoff);
            #pragma unroll
            for (int np = 0; np < 4; np++) {
                uint32_t boff = (np*16 + browb)*128 + ((bcol + ks*32) ^ bsw);
                uint32_t bh0,bh1,bh2,bh3;
                LDSM4(bh0,bh1,bh2,bh3, wHb + boff);
                MMA16816(dacc[2*np][0],dacc[2*np][1],dacc[2*np][2],dacc[2*np][3],
                         ah0,ah1,ah2,ah3, bh0,bh1);
                MMA16816(dacc[2*np+1][0],dacc[2*np+1][1],dacc[2*np+1][2],dacc[2*np+1][3],
                         ah0,ah1,ah2,ah3, bh2,bh3);
            }
        }
    }

    // epilogue: +bias, store y, fused BN stats
    __syncthreads();
    if (tid < 128) psm[tid] = 0.f;
    __syncthreads();

    int px = p0 + wid*16 + g;
    float ss[8], sh[8], qs[8], qh[8];
    #pragma unroll
    for (int nt = 0; nt < 8; nt++) {
        int o = nt*8 + 2*tc;
        float b0 = bias[o], b1 = bias[o+1];
        float v00 = dacc[nt][0] + b0, v01 = dacc[nt][1] + b1;
        float v10 = dacc[nt][2] + b0, v11 = dacc[nt][3] + b1;
        *(float2*)&g_y[(size_t)px*64 + o]     = make_float2(v00, v01);
        *(float2*)&g_y[(size_t)(px+8)*64 + o] = make_float2(v10, v11);
        ss[nt] = v00 + v10;        sh[nt] = v01 + v11;
        qs[nt] = v00*v00 + v10*v10; qh[nt] = v01*v01 + v11*v11;
    }
    #pragma unroll
    for (int d = 4; d < 32; d <<= 1) {
        #pragma unroll
        for (int nt = 0; nt < 8; nt++) {
            ss[nt] += __shfl_xor_sync(0xffffffffu, ss[nt], d);
            sh[nt] += __shfl_xor_sync(0xffffffffu, sh[nt], d);
            qs[nt] += __shfl_xor_sync(0xffffffffu, qs[nt], d);
            qh[nt] += __shfl_xor_sync(0xffffffffu, qh[nt], d);
        }
    }
    if (lane < 4) {
        #pragma unroll
        for (int nt = 0; nt < 8; nt++) {
            int o = nt*8 + 2*tc;
            atomicAdd(&psm[o],       ss[nt]);
            atomicAdd(&psm[o+1],     sh[nt]);
            atomicAdd(&psm[64+o],    qs[nt]);
            atomicAdd(&psm[64+o+1],  qh[nt]);
        }
    }
    __syncthreads();
    if (tid < 64) {
        atomicAdd(&g_sum[tid], psm[tid]);
        atomicAdd(&g_sq [tid], psm[64+tid]);
    }
}

// ---------------------------------------------------------------------------
__global__ __launch_bounds__(1024) void k_norm_out(
    const float* __restrict__ gamma, const float* __restrict__ beta,
    float* __restrict__ out)
{
    __shared__ float t[32][33];
    int w0 = blockIdx.x * 32, c0 = blockIdx.y * 32;
    int bh = blockIdx.z;
    int b = bh / Hn, h = bh % Hn;
    int tx = threadIdx.x, ty = threadIdx.y;

    int c = c0 + tx;
    const float inv = 1.0f / (float)PIX;
    float mean = g_sum[c] * inv;
    float var  = g_sq[c] * inv - mean*mean;
    float rstd = rsqrtf(var + 1e-5f);
    float sc = gamma[c] * rstd;
    float sh = beta[c] - mean * sc;

    float v = g_y[((size_t)bh*Wn + (w0+ty))*Cn + c];
    t[ty][tx] = fmaxf(v*sc + sh, 0.f);
    __syncthreads();
    out[(((size_t)b*Cn + (c0+ty))*Hn + h)*Wn + (w0+tx)] = t[tx][ty];
}

// ---------------------------------------------------------------------------
extern "C" void kernel_launch(void* const* d_in, const int* in_sizes, int n_in,
                              void* d_out, int out_size)
{
    const float* x     = (const float*)d_in[0];
    const float* off_w = (const float*)d_in[1];
    const float* off_b = (const float*)d_in[2];
    const float* mod_w = (const float*)d_in[3];
    const float* mod_b = (const float*)d_in[4];
    const float* wmat  = (const float*)d_in[5];
    const float* bias  = (const float*)d_in[6];
    const float* gamma = (const float*)d_in[7];
    const float* beta  = (const float*)d_in[8];
    float* out = (float*)d_out;

    static int configured = 0;
    if (!configured) {
        cudaFuncSetAttribute(k_conv, cudaFuncAttributeMaxDynamicSharedMemorySize, FSM);
        configured = 1;
    }

    dim3 tgrid(Wn/32, Cn/32, Bn*Hn);
    dim3 tblk(32, 32);

    k_zero<<<1, 64>>>();
    k_wprep<<<64, 256>>>(wmat, off_w, mod_w);
    k_transpose_in<<<tgrid, tblk>>>(x);
    k_conv<<<PIX/128, 256, FSM>>>(off_b, mod_b, bias);
    k_norm_out<<<tgrid, tblk>>>(gamma, beta, out);
}

// round 15
// speedup vs baseline: 1.8482x; 1.0047x over previous
#include <cuda_runtime.h>
#include <cuda_fp16.h>
#include <math.h>
#include <cstdint>

#define Bn   8
#define Cn   64
#define Hn   128
#define Wn   128
#define PIX  (Bn*Hn*Wn)    // 131072

// fused conv smem (bytes):
//  phase1: halo A (392 rows x 128B = 50176) | wH 8192 | om16 7168 | psm 4096
//  phase2: aH 16384 (overlaps halo)         | wH 8192 | om16 7168 | psm 4096
#define F_WH 50176
#define F_OM 58368
#define F_PS 65536
#define FSM  69632

// Scratch
__device__ __half g_x16[PIX*Cn];          // x channels-last fp16 (16.7MB)
__device__ float g_y [PIX*Cn];            // deform out [pix][c]
__device__ __half g_wdh[9*64*64];         // deform W fp16  [tap][o][c]
__device__ __half g_woh[9*32*64];         // offmask W fp16 [tap][o(32)][c]
__device__ float g_sum[Cn];
__device__ float g_sq [Cn];

#define MMA16816(d0,d1,d2,d3,a0,a1,a2,a3,b0,b1) \
    asm volatile("mma.sync.aligned.m16n8k16.row.col.f32.f16.f16.f32 " \
        "{%0,%1,%2,%3}, {%4,%5,%6,%7}, {%8,%9}, {%0,%1,%2,%3};" \
        : "+f"(d0), "+f"(d1), "+f"(d2), "+f"(d3) \
        : "r"(a0), "r"(a1), "r"(a2), "r"(a3), "r"(b0), "r"(b1))

#define LDSM4(r0,r1,r2,r3,a) \
    asm volatile("ldmatrix.sync.aligned.m8n8.x4.shared.b16 {%0,%1,%2,%3}, [%4];" \
        : "=r"(r0), "=r"(r1), "=r"(r2), "=r"(r3) : "r"(a))

__device__ __forceinline__ uint32_t lds_addr(const void* p) {
    return (uint32_t)__cvta_generic_to_shared(p);
}

// ---------------------------------------------------------------------------
__global__ void k_zero() {
    int i = threadIdx.x;
    if (i < Cn) { g_sum[i] = 0.f; g_sq[i] = 0.f; }
}

// ---------------------------------------------------------------------------
__global__ __launch_bounds__(256) void k_wprep(
    const float* __restrict__ wmat,
    const float* __restrict__ off_w, const float* __restrict__ mod_w)
{
    for (int i = blockIdx.x*256 + threadIdx.x; i < 9*4096 + 9*2048; i += gridDim.x*256) {
        if (i < 9*4096) {
            int tap = i >> 12, r = i & 4095;
            int o = r >> 6, c = r & 63;
            g_wdh[i] = __float2half_rn(wmat[(o*64 + c)*9 + tap]);
        } else {
            int j = i - 9*4096;
            int tap = j >> 11, r = j & 2047;
            int o = r >> 6, c = r & 63;
            float v = 0.f;
            if (o < 18)      v = off_w[(o*64 + c)*9 + tap];
            else if (o < 27) v = mod_w[((o-18)*64 + c)*9 + tap];
            g_woh[j] = __float2half_rn(v);
        }
    }
}

// ---------------------------------------------------------------------------
// x[b][c][h][w] (fp32) -> g_x16[((b*H+h)*W+w)*C + c] (fp16)
__global__ __launch_bounds__(1024) void k_transpose_in(const float* __restrict__ x) {
    __shared__ float t[32][33];
    int w0 = blockIdx.x * 32, c0 = blockIdx.y * 32;
    int bh = blockIdx.z;
    int b = bh / Hn, h = bh % Hn;
    int tx = threadIdx.x, ty = threadIdx.y;
    t[ty][tx] = x[(((b*Cn) + (c0+ty))*Hn + h)*Wn + (w0+tx)];
    __syncthreads();
    g_x16[((size_t)bh*Wn + (w0+ty))*Cn + (c0+tx)] = __float2half_rn(t[tx][ty]);
}

// ---------------------------------------------------------------------------
// FUSED conv. Block = 1 row (128 px), 256 thr.
// Phase 1: halo staged ONCE; offmask GEMM via row-shifted LDSM -> om16 smem.
// Phase 2: deform GEMM (gather via om16), fused BN stats.
__global__ __launch_bounds__(256) void k_conv(
    const float* __restrict__ off_b, const float* __restrict__ mod_b,
    const float* __restrict__ bias)
{
    extern __shared__ __align__(16) char sm[];
    char* wH = sm + F_WH;
    __half* om16 = (__half*)(sm + F_OM);   // [128][28]
    float* psm = (float*)(sm + F_PS);      // [128][8]
    uint32_t smB = lds_addr(sm), wHb = lds_addr(wH);

    int tid = threadIdx.x;
    int wid = tid >> 5, lane = tid & 31;
    int g = lane >> 2, tc = lane & 3;
    int lrow = lane & 7, lmat = lane >> 3;
    int blk = blockIdx.x;
    int b = blk >> 7, h = blk & 127;
    int p0 = blk * 128;
    int c8 = tid & 7, grp8 = tid >> 3;

    // fragment addressing
    int apx  = wid*16 + ((lmat & 1) << 3) + lrow;   // pixel index this thread covers
    int acol = (lmat >> 1) << 4;
    int browb = ((lmat >> 1) << 3) + lrow;
    int bsw  = (browb & 7) << 4;
    int bcol = (lmat & 1) << 4;

    // ============================ PHASE 1: offmask =========================
    {
        // stage 3-row x 130-px halo (fp16, 16B lanes), zero padded
        for (int i = tid; i < 390*8; i += 256) {
            int rc = i >> 3, c8i = i & 7;
            int ky = rc / 130, hx = rc - ky*130;
            int y = h + ky - 1, xx = hx - 1;
            uint4 v = make_uint4(0u,0u,0u,0u);
            if (y >= 0 && y < Hn && xx >= 0 && xx < Wn)
                v = *(const uint4*)&g_x16[(((size_t)b*Hn + y)*Wn + xx)*Cn + c8i*8];
            int off = rc*128 + ((c8i*16) ^ ((rc & 7)*16));
            *(uint4*)(sm + off) = v;
        }

        float dacc[4][4];
        #pragma unroll
        for (int n = 0; n < 4; n++)
            #pragma unroll
            for (int q = 0; q < 4; q++) dacc[n][q] = 0.f;

        for (int tap = 0; tap < 9; tap++) {
            __syncthreads();   // halo ready (tap 0) / prev MMA done before W overwrite
            for (int i = tid; i < 256; i += 256) {
                int row = i >> 3, q = i & 7;
                int off = row*128 + ((q*16) ^ ((row & 7)*16));
                *(uint4*)(wH + off) = ((const uint4*)&g_woh[tap*2048])[i];
            }
            __syncthreads();   // W ready
            int ky = tap/3, kx = tap - ky*3 - 1;
            int rcb = ky*130 + apx + kx + 1;       // halo row for this thread
            uint32_t aRow = rcb*128;
            int asw = (rcb & 7) << 4;
            #pragma unroll
            for (int ks = 0; ks < 4; ks++) {
                uint32_t aoff = aRow + ((acol + ks*32) ^ asw);
                uint32_t ah0,ah1,ah2,ah3;
                LDSM4(ah0,ah1,ah2,ah3, smB + aoff);
                #pragma unroll
                for (int np = 0; np < 2; np++) {
                    uint32_t boff = (np*16 + browb)*128 + ((bcol + ks*32) ^ bsw);
                    uint32_t bh0,bh1,bh2,bh3;
                    LDSM4(bh0,bh1,bh2,bh3, wHb + boff);
                    MMA16816(dacc[2*np][0],dacc[2*np][1],dacc[2*np][2],dacc[2*np][3],
                             ah0,ah1,ah2,ah3, bh0,bh1);
                    MMA16816(dacc[2*np+1][0],dacc[2*np+1][1],dacc[2*np+1][2],dacc[2*np+1][3],
                             ah0,ah1,ah2,ah3, bh2,bh3);
                }
            }
        }
        // epilogue -> om16 smem
        __syncthreads();
        int lpx = wid*16 + g;
        #pragma unroll
        for (int nt = 0; nt < 4; nt++) {
            int o = nt*8 + 2*tc;
            #pragma unroll
            for (int j = 0; j < 2; j++) {
                int oo = o + j;
                if (oo >= 27) continue;
                float v0 = dacc[nt][j], v1 = dacc[nt][2+j];
                if (oo < 18) { float bv = off_b[oo]; v0 += bv; v1 += bv; }
                else {
                    float bv = mod_b[oo-18];
                    v0 = 2.0f / (1.0f + expf(-(v0 + bv)));
                    v1 = 2.0f / (1.0f + expf(-(v1 + bv)));
                }
                om16[lpx*28 + oo]     = __float2half_rn(v0);
                om16[(lpx+8)*28 + oo] = __float2half_rn(v1);
            }
        }
    }

    // ============================ PHASE 2: deform ==========================
    float dacc[8][4];
    #pragma unroll
    for (int n = 0; n < 8; n++)
        #pragma unroll
        for (int q = 0; q < 4; q++) dacc[n][q] = 0.f;

    uint32_t aRowOff = apx*128;
    int asw2 = (apx & 7) << 4;

    for (int tap = 0; tap < 9; tap++) {
        __syncthreads();
        // stage W (64 rows x 128B)
        for (int i = tid; i < 512; i += 256) {
            int row = i >> 3, q = i & 7;
            int off = row*128 + ((q*16) ^ ((row & 7)*16));
            *(uint4*)(wH + off) = ((const uint4*)&g_wdh[tap*4096])[i];
        }
        // bilinear params (threads 0..127, one pixel each; om16 from SMEM)
        if (tid < 128) {
            const __half* omp = &om16[tid*28];
            float dy = __half2float(omp[tap*2]);
            float dx = __half2float(omp[tap*2+1]);
            float mk = __half2float(omp[18+tap]);
            float py = (float)(h + tap/3 - 1) + dy;
            float px_ = (float)(tid + tap%3 - 1) + dx;
            float fy = floorf(py), fx = floorf(px_);
            float ly = py - fy,    lx = px_ - fx;
            int y0 = (int)fy, x0 = (int)fx;
            int y1 = y0 + 1,  x1 = x0 + 1;
            float vy0 = (y0 >= 0 && y0 < Hn) ? 1.f : 0.f;
            float vy1 = (y1 >= 0 && y1 < Hn) ? 1.f : 0.f;
            float vx0 = (x0 >= 0 && x0 < Wn) ? 1.f : 0.f;
            float vx1 = (x1 >= 0 && x1 < Wn) ? 1.f : 0.f;
            int iy0 = min(max(y0,0),Hn-1), iy1 = min(max(y1,0),Hn-1);
            int ix0 = min(max(x0,0),Wn-1), ix1 = min(max(x1,0),Wn-1);
            int base = (b*Hn)*Wn;
            psm[tid*8+0] = (1.f-ly)*(1.f-lx)*mk * vy0*vx0;
            psm[tid*8+1] = (1.f-ly)*lx      *mk * vy0*vx1;
            psm[tid*8+2] = ly      *(1.f-lx)*mk * vy1*vx0;
            psm[tid*8+3] = ly      *lx      *mk * vy1*vx1;
            psm[tid*8+4] = __int_as_float(base + iy0*Wn + ix0);
            psm[tid*8+5] = __int_as_float(base + iy0*Wn + ix1);
            psm[tid*8+6] = __int_as_float(base + iy1*Wn + ix0);
            psm[tid*8+7] = __int_as_float(base + iy1*Wn + ix1);
        }
        __syncthreads();
        // gather (16B lanes: 8 lanes/px) + fp32 blend + fp16 store
        #pragma unroll
        for (int it = 0; it < 4; it++) {
            int px = it*32 + grp8;
            float w00 = psm[px*8+0], w01 = psm[px*8+1];
            float w10 = psm[px*8+2], w11 = psm[px*8+3];
            int i00 = __float_as_int(psm[px*8+4]);
            int i01 = __float_as_int(psm[px*8+5]);
            int i10 = __float_as_int(psm[px*8+6]);
            int i11 = __float_as_int(psm[px*8+7]);
            uint4 ua = *(const uint4*)&g_x16[(size_t)i00*Cn + c8*8];
            uint4 ue = *(const uint4*)&g_x16[(size_t)i01*Cn + c8*8];
            uint4 uc = *(const uint4*)&g_x16[(size_t)i10*Cn + c8*8];
            uint4 ud = *(const uint4*)&g_x16[(size_t)i11*Cn + c8*8];
            uint4 outv;
            const uint32_t* pa = &ua.x;
            const uint32_t* pe = &ue.x;
            const uint32_t* pc = &uc.x;
            const uint32_t* pd = &ud.x;
            uint32_t* po = &outv.x;
            #pragma unroll
            for (int j = 0; j < 4; j++) {
                float2 av = __half22float2(*(const __half2*)&pa[j]);
                float2 ev = __half22float2(*(const __half2*)&pe[j]);
                float2 cv = __half22float2(*(const __half2*)&pc[j]);
                float2 dv = __half22float2(*(const __half2*)&pd[j]);
                float2 v;
                v.x = w00*av.x + w01*ev.x + w10*cv.x + w11*dv.x;
                v.y = w00*av.y + w01*ev.y + w10*cv.y + w11*dv.y;
                __half2 r = __float22half2_rn(v);
                po[j] = *(const uint32_t*)&r;
            }
            int off = px*128 + ((c8*16) ^ ((px & 7)*16));
            *(uint4*)(sm + off) = outv;
        }
        __syncthreads();
        #pragma unroll
        for (int ks = 0; ks < 4; ks++) {
            uint32_t aoff = aRowOff + ((acol + ks*32) ^ asw2);
            uint32_t ah0,ah1,ah2,ah3;
            LDSM4(ah0,ah1,ah2,ah3, smB + aoff);
            #pragma unroll
            for (int np = 0; np < 4; np++) {
                uint32_t boff = (np*16 + browb)*128 + ((bcol + ks*32) ^ bsw);
                uint32_t bh0,bh1,bh2,bh3;
                LDSM4(bh0,bh1,bh2,bh3, wHb + boff);
                MMA16816(dacc[2*np][0],dacc[2*np][1],dacc[2*np][2],dacc[2*np][3],
                         ah0,ah1,ah2,ah3, bh0,bh1);
                MMA16816(dacc[2*np+1][0],dacc[2*np+1][1],dacc[2*np+1][2],dacc[2*np+1][3],
                         ah0,ah1,ah2,ah3, bh2,bh3);
            }
        }
    }

    // epilogue: +bias, store y, fused BN stats
    __syncthreads();
    if (tid < 128) psm[tid] = 0.f;
    __syncthreads();

    int px = p0 + wid*16 + g;
    float ss[8], sh[8], qs[8], qh[8];
    #pragma unroll
    for (int nt = 0; nt < 8; nt++) {
        int o = nt*8 + 2*tc;
        float b0 = bias[o], b1 = bias[o+1];
        float v00 = dacc[nt][0] + b0, v01 = dacc[nt][1] + b1;
        float v10 = dacc[nt][2] + b0, v11 = dacc[nt][3] + b1;
        *(float2*)&g_y[(size_t)px*64 + o]     = make_float2(v00, v01);
        *(float2*)&g_y[(size_t)(px+8)*64 + o] = make_float2(v10, v11);
        ss[nt] = v00 + v10;        sh[nt] = v01 + v11;
        qs[nt] = v00*v00 + v10*v10; qh[nt] = v01*v01 + v11*v11;
    }
    #pragma unroll
    for (int d = 4; d < 32; d <<= 1) {
        #pragma unroll
        for (int nt = 0; nt < 8; nt++) {
            ss[nt] += __shfl_xor_sync(0xffffffffu, ss[nt], d);
            sh[nt] += __shfl_xor_sync(0xffffffffu, sh[nt], d);
            qs[nt] += __shfl_xor_sync(0xffffffffu, qs[nt], d);
            qh[nt] += __shfl_xor_sync(0xffffffffu, qh[nt], d);
        }
    }
    if (lane < 4) {
        #pragma unroll
        for (int nt = 0; nt < 8; nt++) {
            int o = nt*8 + 2*tc;
            atomicAdd(&psm[o],       ss[nt]);
            atomicAdd(&psm[o+1],     sh[nt]);
            atomicAdd(&psm[64+o],    qs[nt]);
            atomicAdd(&psm[64+o+1],  qh[nt]);
        }
    }
    __syncthreads();
    if (tid < 64) {
        atomicAdd(&g_sum[tid], psm[tid]);
        atomicAdd(&g_sq [tid], psm[64+tid]);
    }
}

// ---------------------------------------------------------------------------
__global__ __launch_bounds__(1024) void k_norm_out(
    const float* __restrict__ gamma, const float* __restrict__ beta,
    float* __restrict__ out)
{
    __shared__ float t[32][33];
    int w0 = blockIdx.x * 32, c0 = blockIdx.y * 32;
    int bh = blockIdx.z;
    int b = bh / Hn, h = bh % Hn;
    int tx = threadIdx.x, ty = threadIdx.y;

    int c = c0 + tx;
    const float inv = 1.0f / (float)PIX;
    float mean = g_sum[c] * inv;
    float var  = g_sq[c] * inv - mean*mean;
    float rstd = rsqrtf(var + 1e-5f);
    float sc = gamma[c] * rstd;
    float sh = beta[c] - mean * sc;

    float v = g_y[((size_t)bh*Wn + (w0+ty))*Cn + c];
    t[ty][tx] = fmaxf(v*sc + sh, 0.f);
    __syncthreads();
    out[(((size_t)b*Cn + (c0+ty))*Hn + h)*Wn + (w0+tx)] = t[tx][ty];
}

// ---------------------------------------------------------------------------
extern "C" void kernel_launch(void* const* d_in, const int* in_sizes, int n_in,
                              void* d_out, int out_size)
{
    const float* x     = (const float*)d_in[0];
    const float* off_w = (const float*)d_in[1];
    const float* off_b = (const float*)d_in[2];
    const float* mod_w = (const float*)d_in[3];
    const float* mod_b = (const float*)d_in[4];
    const float* wmat  = (const float*)d_in[5];
    const float* bias  = (const float*)d_in[6];
    const float* gamma = (const float*)d_in[7];
    const float* beta  = (const float*)d_in[8];
    float* out = (float*)d_out;

    static int configured = 0;
    if (!configured) {
        cudaFuncSetAttribute(k_conv, cudaFuncAttributeMaxDynamicSharedMemorySize, FSM);
        configured = 1;
    }

    dim3 tgrid(Wn/32, Cn/32, Bn*Hn);
    dim3 tblk(32, 32);

    k_zero<<<1, 64>>>();
    k_wprep<<<64, 256>>>(wmat, off_w, mod_w);
    k_transpose_in<<<tgrid, tblk>>>(x);
    k_conv<<<PIX/128, 256, FSM>>>(off_b, mod_b, bias);
    k_norm_out<<<tgrid, tblk>>>(gamma, beta, out);
}

// round 16
// speedup vs baseline: 1.9561x; 1.0584x over previous
#include <cuda_runtime.h>
#include <cuda_fp16.h>
#include <math.h>
#include <cstdint>

#define Bn   8
#define Cn   64
#define Hn   128
#define Wn   128
#define PIX  (Bn*Hn*Wn)    // 131072

// fused conv smem (bytes): aH 16384 | wH 8192 | om16 7168 | psm 4096
#define F_WH 16384
#define F_OM 24576
#define F_PS 31744
#define FSM  35840

// Scratch
__device__ __half g_x16[PIX*Cn];          // x channels-last fp16 (16.7MB)
__device__ float g_y [PIX*Cn];            // deform out [pix][c]
__device__ __half g_wdh[9*64*64];         // deform W fp16  [tap][o][c]
__device__ __half g_woh[9*32*64];         // offmask W fp16 [tap][o(32)][c]
__device__ float g_sum[Cn];
__device__ float g_sq [Cn];

#define MMA16816(d0,d1,d2,d3,a0,a1,a2,a3,b0,b1) \
    asm volatile("mma.sync.aligned.m16n8k16.row.col.f32.f16.f16.f32 " \
        "{%0,%1,%2,%3}, {%4,%5,%6,%7}, {%8,%9}, {%0,%1,%2,%3};" \
        : "+f"(d0), "+f"(d1), "+f"(d2), "+f"(d3) \
        : "r"(a0), "r"(a1), "r"(a2), "r"(a3), "r"(b0), "r"(b1))

#define LDSM4(r0,r1,r2,r3,a) \
    asm volatile("ldmatrix.sync.aligned.m8n8.x4.shared.b16 {%0,%1,%2,%3}, [%4];" \
        : "=r"(r0), "=r"(r1), "=r"(r2), "=r"(r3) : "r"(a))

__device__ __forceinline__ uint32_t lds_addr(const void* p) {
    return (uint32_t)__cvta_generic_to_shared(p);
}

// ---------------------------------------------------------------------------
__global__ void k_zero() {
    int i = threadIdx.x;
    if (i < Cn) { g_sum[i] = 0.f; g_sq[i] = 0.f; }
}

// ---------------------------------------------------------------------------
__global__ __launch_bounds__(256) void k_wprep(
    const float* __restrict__ wmat,
    const float* __restrict__ off_w, const float* __restrict__ mod_w)
{
    for (int i = blockIdx.x*256 + threadIdx.x; i < 9*4096 + 9*2048; i += gridDim.x*256) {
        if (i < 9*4096) {
            int tap = i >> 12, r = i & 4095;
            int o = r >> 6, c = r & 63;
            g_wdh[i] = __float2half_rn(wmat[(o*64 + c)*9 + tap]);
        } else {
            int j = i - 9*4096;
            int tap = j >> 11, r = j & 2047;
            int o = r >> 6, c = r & 63;
            float v = 0.f;
            if (o < 18)      v = off_w[(o*64 + c)*9 + tap];
            else if (o < 27) v = mod_w[((o-18)*64 + c)*9 + tap];
            g_woh[j] = __float2half_rn(v);
        }
    }
}

// ---------------------------------------------------------------------------
// x[b][c][h][w] (fp32) -> g_x16[((b*H+h)*W+w)*C + c] (fp16)
__global__ __launch_bounds__(1024) void k_transpose_in(const float* __restrict__ x) {
    __shared__ float t[32][33];
    int w0 = blockIdx.x * 32, c0 = blockIdx.y * 32;
    int bh = blockIdx.z;
    int b = bh / Hn, h = bh % Hn;
    int tx = threadIdx.x, ty = threadIdx.y;
    t[ty][tx] = x[(((b*Cn) + (c0+ty))*Hn + h)*Wn + (w0+tx)];
    __syncthreads();
    g_x16[((size_t)bh*Wn + (w0+ty))*Cn + (c0+tx)] = __float2half_rn(t[tx][ty]);
}

// ---------------------------------------------------------------------------
// FUSED conv. Block = 1 row (128 px), 256 thr.
__global__ __launch_bounds__(256) void k_conv(
    const float* __restrict__ off_b, const float* __restrict__ mod_b,
    const float* __restrict__ bias)
{
    extern __shared__ __align__(16) char sm[];
    char* aH = sm;
    char* wH = sm + F_WH;
    __half* om16 = (__half*)(sm + F_OM);   // [128][28]
    float* psm = (float*)(sm + F_PS);      // [128][8]
    uint32_t aHb = lds_addr(aH), wHb = lds_addr(wH);

    int tid = threadIdx.x;
    int wid = tid >> 5, lane = tid & 31;
    int g = lane >> 2, tc = lane & 3;
    int lrow = lane & 7, lmat = lane >> 3;
    int blk = blockIdx.x;
    int b = blk >> 7, h = blk & 127;
    int p0 = blk * 128;
    int c8 = tid & 7, grp8 = tid >> 3;

    int arow = wid*16 + ((lmat & 1) << 3) + lrow;
    uint32_t aRowOff = arow*128;
    int asw  = (arow & 7) << 4;
    int acol = (lmat >> 1) << 4;
    int browb = ((lmat >> 1) << 3) + lrow;
    int bsw  = (browb & 7) << 4;
    int bcol = (lmat & 1) << 4;

    // ============================ PHASE 1: offmask =========================
    {
        float dacc[4][4];
        #pragma unroll
        for (int n = 0; n < 4; n++)
            #pragma unroll
            for (int q = 0; q < 4; q++) dacc[n][q] = 0.f;

        for (int tap = 0; tap < 9; tap++) {
            __syncthreads();
            for (int i = tid; i < 256; i += 256) {
                int row = i >> 3, q = i & 7;
                int off = row*128 + ((q*16) ^ ((row & 7)*16));
                *(uint4*)(wH + off) = ((const uint4*)&g_woh[tap*2048])[i];
            }
            int y = h + tap/3 - 1;
            int dxs = tap%3 - 1;
            #pragma unroll
            for (int it = 0; it < 4; it++) {
                int px = it*32 + grp8;
                int xx = px + dxs;
                uint4 v = make_uint4(0u,0u,0u,0u);
                if (y >= 0 && y < Hn && xx >= 0 && xx < Wn)
                    v = *(const uint4*)&g_x16[(((size_t)b*Hn + y)*Wn + xx)*Cn + c8*8];
                int off = px*128 + ((c8*16) ^ ((px & 7)*16));
                *(uint4*)(aH + off) = v;
            }
            __syncthreads();
            #pragma unroll
            for (int ks = 0; ks < 4; ks++) {
                uint32_t aoff = aRowOff + ((acol + ks*32) ^ asw);
                uint32_t ah0,ah1,ah2,ah3;
                LDSM4(ah0,ah1,ah2,ah3, aHb + aoff);
                #pragma unroll
                for (int np = 0; np < 2; np++) {
                    uint32_t boff = (np*16 + browb)*128 + ((bcol + ks*32) ^ bsw);
                    uint32_t bh0,bh1,bh2,bh3;
                    LDSM4(bh0,bh1,bh2,bh3, wHb + boff);
                    MMA16816(dacc[2*np][0],dacc[2*np][1],dacc[2*np][2],dacc[2*np][3],
                             ah0,ah1,ah2,ah3, bh0,bh1);
                    MMA16816(dacc[2*np+1][0],dacc[2*np+1][1],dacc[2*np+1][2],dacc[2*np+1][3],
                             ah0,ah1,ah2,ah3, bh2,bh3);
                }
            }
        }
        // epilogue -> om16 smem
        __syncthreads();
        int lpx = wid*16 + g;
        #pragma unroll
        for (int nt = 0; nt < 4; nt++) {
            int o = nt*8 + 2*tc;
            #pragma unroll
            for (int j = 0; j < 2; j++) {
                int oo = o + j;
                if (oo >= 27) continue;
                float v0 = dacc[nt][j], v1 = dacc[nt][2+j];
                if (oo < 18) { float bv = off_b[oo]; v0 += bv; v1 += bv; }
                else {
                    float bv = mod_b[oo-18];
                    v0 = 2.0f / (1.0f + expf(-(v0 + bv)));
                    v1 = 2.0f / (1.0f + expf(-(v1 + bv)));
                }
                om16[lpx*28 + oo]     = __float2half_rn(v0);
                om16[(lpx+8)*28 + oo] = __float2half_rn(v1);
            }
        }
    }

    // ============================ PHASE 2: deform ==========================
    float dacc[8][4];
    #pragma unroll
    for (int n = 0; n < 8; n++)
        #pragma unroll
        for (int q = 0; q < 4; q++) dacc[n][q] = 0.f;

    for (int tap = 0; tap < 9; tap++) {
        __syncthreads();
        // stage W (64 rows x 128B)
        for (int i = tid; i < 512; i += 256) {
            int row = i >> 3, q = i & 7;
            int off = row*128 + ((q*16) ^ ((row & 7)*16));
            *(uint4*)(wH + off) = ((const uint4*)&g_wdh[tap*4096])[i];
        }
        // bilinear params (threads 0..127, one pixel each)
        if (tid < 128) {
            const __half* omp = &om16[tid*28];
            float dy = __half2float(omp[tap*2]);
            float dx = __half2float(omp[tap*2+1]);
            float mk = __half2float(omp[18+tap]);
            float py = (float)(h + tap/3 - 1) + dy;
            float px_ = (float)(tid + tap%3 - 1) + dx;
            float fy = floorf(py), fx = floorf(px_);
            float ly = py - fy,    lx = px_ - fx;
            int y0 = (int)fy, x0 = (int)fx;
            int y1 = y0 + 1,  x1 = x0 + 1;
            float vy0 = (y0 >= 0 && y0 < Hn) ? 1.f : 0.f;
            float vy1 = (y1 >= 0 && y1 < Hn) ? 1.f : 0.f;
            float vx0 = (x0 >= 0 && x0 < Wn) ? 1.f : 0.f;
            float vx1 = (x1 >= 0 && x1 < Wn) ? 1.f : 0.f;
            int iy0 = min(max(y0,0),Hn-1), iy1 = min(max(y1,0),Hn-1);
            int ix0 = min(max(x0,0),Wn-1), ix1 = min(max(x1,0),Wn-1);
            int base = (b*Hn)*Wn;
            psm[tid*8+0] = (1.f-ly)*(1.f-lx)*mk * vy0*vx0;
            psm[tid*8+1] = (1.f-ly)*lx      *mk * vy0*vx1;
            psm[tid*8+2] = ly      *(1.f-lx)*mk * vy1*vx0;
            psm[tid*8+3] = ly      *lx      *mk * vy1*vx1;
            psm[tid*8+4] = __int_as_float(base + iy0*Wn + ix0);
            psm[tid*8+5] = __int_as_float(base + iy0*Wn + ix1);
            psm[tid*8+6] = __int_as_float(base + iy1*Wn + ix0);
            psm[tid*8+7] = __int_as_float(base + iy1*Wn + ix1);
        }
        __syncthreads();
        // gather (16B lanes) + HALF2 blend (HFMA2) + store
        #pragma unroll
        for (int it = 0; it < 4; it++) {
            int px = it*32 + grp8;
            __half2 W00 = __float2half2_rn(psm[px*8+0]);
            __half2 W01 = __float2half2_rn(psm[px*8+1]);
            __half2 W10 = __float2half2_rn(psm[px*8+2]);
            __half2 W11 = __float2half2_rn(psm[px*8+3]);
            int i00 = __float_as_int(psm[px*8+4]);
            int i01 = __float_as_int(psm[px*8+5]);
            int i10 = __float_as_int(psm[px*8+6]);
            int i11 = __float_as_int(psm[px*8+7]);
            uint4 ua = *(const uint4*)&g_x16[(size_t)i00*Cn + c8*8];
            uint4 ue = *(const uint4*)&g_x16[(size_t)i01*Cn + c8*8];
            uint4 uc = *(const uint4*)&g_x16[(size_t)i10*Cn + c8*8];
            uint4 ud = *(const uint4*)&g_x16[(size_t)i11*Cn + c8*8];
            uint4 outv;
            const uint32_t* pa = &ua.x;
            const uint32_t* pe = &ue.x;
            const uint32_t* pc = &uc.x;
            const uint32_t* pd = &ud.x;
            uint32_t* po = &outv.x;
            #pragma unroll
            for (int j = 0; j < 4; j++) {
                __half2 av = *(const __half2*)&pa[j];
                __half2 ev = *(const __half2*)&pe[j];
                __half2 cv = *(const __half2*)&pc[j];
                __half2 dv = *(const __half2*)&pd[j];
                __half2 r = __hfma2(av, W00,
                            __hfma2(ev, W01,
                            __hfma2(cv, W10, __hmul2(dv, W11))));
                po[j] = *(const uint32_t*)&r;
            }
            int off = px*128 + ((c8*16) ^ ((px & 7)*16));
            *(uint4*)(aH + off) = outv;
        }
        __syncthreads();
        #pragma unroll
        for (int ks = 0; ks < 4; ks++) {
            uint32_t aoff = aRowOff + ((acol + ks*32) ^ asw);
            uint32_t ah0,ah1,ah2,ah3;
            LDSM4(ah0,ah1,ah2,ah3, aHb + aoff);
            #pragma unroll
            for (int np = 0; np < 4; np++) {
                uint32_t boff = (np*16 + browb)*128 + ((bcol + ks*32) ^ bsw);
                uint32_t bh0,bh1,bh2,bh3;
                LDSM4(bh0,bh1,bh2,bh3, wHb + boff);
                MMA16816(dacc[2*np][0],dacc[2*np][1],dacc[2*np][2],dacc[2*np][3],
                         ah0,ah1,ah2,ah3, bh0,bh1);
                MMA16816(dacc[2*np+1][0],dacc[2*np+1][1],dacc[2*np+1][2],dacc[2*np+1][3],
                         ah0,ah1,ah2,ah3, bh2,bh3);
            }
        }
    }

    // epilogue: +bias, store y, fused BN stats
    __syncthreads();
    if (tid < 128) psm[tid] = 0.f;
    __syncthreads();

    int px = p0 + wid*16 + g;
    float ss[8], sh[8], qs[8], qh[8];
    #pragma unroll
    for (int nt = 0; nt < 8; nt++) {
        int o = nt*8 + 2*tc;
        float b0 = bias[o], b1 = bias[o+1];
        float v00 = dacc[nt][0] + b0, v01 = dacc[nt][1] + b1;
        float v10 = dacc[nt][2] + b0, v11 = dacc[nt][3] + b1;
        *(float2*)&g_y[(size_t)px*64 + o]     = make_float2(v00, v01);
        *(float2*)&g_y[(size_t)(px+8)*64 + o] = make_float2(v10, v11);
        ss[nt] = v00 + v10;        sh[nt] = v01 + v11;
        qs[nt] = v00*v00 + v10*v10; qh[nt] = v01*v01 + v11*v11;
    }
    #pragma unroll
    for (int d = 4; d < 32; d <<= 1) {
        #pragma unroll
        for (int nt = 0; nt < 8; nt++) {
            ss[nt] += __shfl_xor_sync(0xffffffffu, ss[nt], d);
            sh[nt] += __shfl_xor_sync(0xffffffffu, sh[nt], d);
            qs[nt] += __shfl_xor_sync(0xffffffffu, qs[nt], d);
            qh[nt] += __shfl_xor_sync(0xffffffffu, qh[nt], d);
        }
    }
    if (lane < 4) {
        #pragma unroll
        for (int nt = 0; nt < 8; nt++) {
            int o = nt*8 + 2*tc;
            atomicAdd(&psm[o],       ss[nt]);
            atomicAdd(&psm[o+1],     sh[nt]);
            atomicAdd(&psm[64+o],    qs[nt]);
            atomicAdd(&psm[64+o+1],  qh[nt]);
        }
    }
    __syncthreads();
    if (tid < 64) {
        atomicAdd(&g_sum[tid], psm[tid]);
        atomicAdd(&g_sq [tid], psm[64+tid]);
    }
}

// ---------------------------------------------------------------------------
__global__ __launch_bounds__(1024) void k_norm_out(
    const float* __restrict__ gamma, const float* __restrict__ beta,
    float* __restrict__ out)
{
    __shared__ float t[32][33];
    int w0 = blockIdx.x * 32, c0 = blockIdx.y * 32;
    int bh = blockIdx.z;
    int b = bh / Hn, h = bh % Hn;
    int tx = threadIdx.x, ty = threadIdx.y;

    int c = c0 + tx;
    const float inv = 1.0f / (float)PIX;
    float mean = g_sum[c] * inv;
    float var  = g_sq[c] * inv - mean*mean;
    float rstd = rsqrtf(var + 1e-5f);
    float sc = gamma[c] * rstd;
    float sh = beta[c] - mean * sc;

    float v = g_y[((size_t)bh*Wn + (w0+ty))*Cn + c];
    t[ty][tx] = fmaxf(v*sc + sh, 0.f);
    __syncthreads();
    out[(((size_t)b*Cn + (c0+ty))*Hn + h)*Wn + (w0+tx)] = t[tx][ty];
}

// ---------------------------------------------------------------------------
extern "C" void kernel_launch(void* const* d_in, const int* in_sizes, int n_in,
                              void* d_out, int out_size)
{
    const float* x     = (const float*)d_in[0];
    const float* off_w = (const float*)d_in[1];
    const float* off_b = (const float*)d_in[2];
    const float* mod_w = (const float*)d_in[3];
    const float* mod_b = (const float*)d_in[4];
    const float* wmat  = (const float*)d_in[5];
    const float* bias  = (const float*)d_in[6];
    const float* gamma = (const float*)d_in[7];
    const float* beta  = (const float*)d_in[8];
    float* out = (float*)d_out;

    static int configured = 0;
    if (!configured) {
        cudaFuncSetAttribute(k_conv, cudaFuncAttributeMaxDynamicSharedMemorySize, FSM);
        configured = 1;
    }

    dim3 tgrid(Wn/32, Cn/32, Bn*Hn);
    dim3 tblk(32, 32);

    k_zero<<<1, 64>>>();
    k_wprep<<<64, 256>>>(wmat, off_w, mod_w);
    k_transpose_in<<<tgrid, tblk>>>(x);
    k_conv<<<PIX/128, 256, FSM>>>(off_b, mod_b, bias);
    k_norm_out<<<tgrid, tblk>>>(gamma, beta, out);
}

// round 17
// speedup vs baseline: 2.0117x; 1.0284x over previous
#include <cuda_runtime.h>
#include <cuda_fp16.h>
#include <math.h>
#include <cstdint>

#define Bn   8
#define Cn   64
#define Hn   128
#define Wn   128
#define PIX  (Bn*Hn*Wn)    // 131072

// fused conv smem (bytes): aH 16384 | wH 8192 | om16 7168 | psm 4096
#define F_WH 16384
#define F_OM 24576
#define F_PS 31744
#define FSM  35840

// Scratch
__device__ __half g_x16[PIX*Cn];          // x channels-last fp16 (16.7MB)
__device__ __half g_y16[PIX*Cn];          // deform out fp16 [pix][c] (16.7MB)
__device__ __half g_wdh[9*64*64];         // deform W fp16  [tap][o][c]
__device__ __half g_woh[9*32*64];         // offmask W fp16 [tap][o(32)][c]
__device__ float g_sum[Cn];
__device__ float g_sq [Cn];

#define MMA16816(d0,d1,d2,d3,a0,a1,a2,a3,b0,b1) \
    asm volatile("mma.sync.aligned.m16n8k16.row.col.f32.f16.f16.f32 " \
        "{%0,%1,%2,%3}, {%4,%5,%6,%7}, {%8,%9}, {%0,%1,%2,%3};" \
        : "+f"(d0), "+f"(d1), "+f"(d2), "+f"(d3) \
        : "r"(a0), "r"(a1), "r"(a2), "r"(a3), "r"(b0), "r"(b1))

#define LDSM4(r0,r1,r2,r3,a) \
    asm volatile("ldmatrix.sync.aligned.m8n8.x4.shared.b16 {%0,%1,%2,%3}, [%4];" \
        : "=r"(r0), "=r"(r1), "=r"(r2), "=r"(r3) : "r"(a))

__device__ __forceinline__ uint32_t lds_addr(const void* p) {
    return (uint32_t)__cvta_generic_to_shared(p);
}

// ---------------------------------------------------------------------------
__global__ void k_zero() {
    int i = threadIdx.x;
    if (i < Cn) { g_sum[i] = 0.f; g_sq[i] = 0.f; }
}

// ---------------------------------------------------------------------------
__global__ __launch_bounds__(256) void k_wprep(
    const float* __restrict__ wmat,
    const float* __restrict__ off_w, const float* __restrict__ mod_w)
{
    for (int i = blockIdx.x*256 + threadIdx.x; i < 9*4096 + 9*2048; i += gridDim.x*256) {
        if (i < 9*4096) {
            int tap = i >> 12, r = i & 4095;
            int o = r >> 6, c = r & 63;
            g_wdh[i] = __float2half_rn(wmat[(o*64 + c)*9 + tap]);
        } else {
            int j = i - 9*4096;
            int tap = j >> 11, r = j & 2047;
            int o = r >> 6, c = r & 63;
            float v = 0.f;
            if (o < 18)      v = off_w[(o*64 + c)*9 + tap];
            else if (o < 27) v = mod_w[((o-18)*64 + c)*9 + tap];
            g_woh[j] = __float2half_rn(v);
        }
    }
}

// ---------------------------------------------------------------------------
// x[b][c][h][w] (fp32) -> g_x16[((b*H+h)*W+w)*C + c] (fp16)
__global__ __launch_bounds__(1024) void k_transpose_in(const float* __restrict__ x) {
    __shared__ float t[32][33];
    int w0 = blockIdx.x * 32, c0 = blockIdx.y * 32;
    int bh = blockIdx.z;
    int b = bh / Hn, h = bh % Hn;
    int tx = threadIdx.x, ty = threadIdx.y;
    t[ty][tx] = x[(((b*Cn) + (c0+ty))*Hn + h)*Wn + (w0+tx)];
    __syncthreads();
    g_x16[((size_t)bh*Wn + (w0+ty))*Cn + (c0+tx)] = __float2half_rn(t[tx][ty]);
}

// ---------------------------------------------------------------------------
// FUSED conv. Block = 1 row (128 px), 256 thr.
__global__ __launch_bounds__(256) void k_conv(
    const float* __restrict__ off_b, const float* __restrict__ mod_b,
    const float* __restrict__ bias)
{
    extern __shared__ __align__(16) char sm[];
    char* aH = sm;
    char* wH = sm + F_WH;
    __half* om16 = (__half*)(sm + F_OM);   // [128][28]
    float* psm = (float*)(sm + F_PS);      // [128][8]
    uint32_t aHb = lds_addr(aH), wHb = lds_addr(wH);

    int tid = threadIdx.x;
    int wid = tid >> 5, lane = tid & 31;
    int g = lane >> 2, tc = lane & 3;
    int lrow = lane & 7, lmat = lane >> 3;
    int blk = blockIdx.x;
    int b = blk >> 7, h = blk & 127;
    int p0 = blk * 128;
    int c8 = tid & 7, grp8 = tid >> 3;

    int arow = wid*16 + ((lmat & 1) << 3) + lrow;
    uint32_t aRowOff = arow*128;
    int asw  = (arow & 7) << 4;
    int acol = (lmat >> 1) << 4;
    int browb = ((lmat >> 1) << 3) + lrow;
    int bsw  = (browb & 7) << 4;
    int bcol = (lmat & 1) << 4;

    // ============================ PHASE 1: offmask =========================
    {
        float dacc[4][4];
        #pragma unroll
        for (int n = 0; n < 4; n++)
            #pragma unroll
            for (int q = 0; q < 4; q++) dacc[n][q] = 0.f;

        for (int tap = 0; tap < 9; tap++) {
            __syncthreads();
            for (int i = tid; i < 256; i += 256) {
                int row = i >> 3, q = i & 7;
                int off = row*128 + ((q*16) ^ ((row & 7)*16));
                *(uint4*)(wH + off) = ((const uint4*)&g_woh[tap*2048])[i];
            }
            int y = h + tap/3 - 1;
            int dxs = tap%3 - 1;
            #pragma unroll
            for (int it = 0; it < 4; it++) {
                int px = it*32 + grp8;
                int xx = px + dxs;
                uint4 v = make_uint4(0u,0u,0u,0u);
                if (y >= 0 && y < Hn && xx >= 0 && xx < Wn)
                    v = *(const uint4*)&g_x16[(((size_t)b*Hn + y)*Wn + xx)*Cn + c8*8];
                int off = px*128 + ((c8*16) ^ ((px & 7)*16));
                *(uint4*)(aH + off) = v;
            }
            __syncthreads();
            #pragma unroll
            for (int ks = 0; ks < 4; ks++) {
                uint32_t aoff = aRowOff + ((acol + ks*32) ^ asw);
                uint32_t ah0,ah1,ah2,ah3;
                LDSM4(ah0,ah1,ah2,ah3, aHb + aoff);
                #pragma unroll
                for (int np = 0; np < 2; np++) {
                    uint32_t boff = (np*16 + browb)*128 + ((bcol + ks*32) ^ bsw);
                    uint32_t bh0,bh1,bh2,bh3;
                    LDSM4(bh0,bh1,bh2,bh3, wHb + boff);
                    MMA16816(dacc[2*np][0],dacc[2*np][1],dacc[2*np][2],dacc[2*np][3],
                             ah0,ah1,ah2,ah3, bh0,bh1);
                    MMA16816(dacc[2*np+1][0],dacc[2*np+1][1],dacc[2*np+1][2],dacc[2*np+1][3],
                             ah0,ah1,ah2,ah3, bh2,bh3);
                }
            }
        }
        // epilogue -> om16 smem
        __syncthreads();
        int lpx = wid*16 + g;
        #pragma unroll
        for (int nt = 0; nt < 4; nt++) {
            int o = nt*8 + 2*tc;
            #pragma unroll
            for (int j = 0; j < 2; j++) {
                int oo = o + j;
                if (oo >= 27) continue;
                float v0 = dacc[nt][j], v1 = dacc[nt][2+j];
                if (oo < 18) { float bv = off_b[oo]; v0 += bv; v1 += bv; }
                else {
                    float bv = mod_b[oo-18];
                    v0 = 2.0f / (1.0f + expf(-(v0 + bv)));
                    v1 = 2.0f / (1.0f + expf(-(v1 + bv)));
                }
                om16[lpx*28 + oo]     = __float2half_rn(v0);
                om16[(lpx+8)*28 + oo] = __float2half_rn(v1);
            }
        }
    }

    // ============================ PHASE 2: deform ==========================
    float dacc[8][4];
    #pragma unroll
    for (int n = 0; n < 8; n++)
        #pragma unroll
        for (int q = 0; q < 4; q++) dacc[n][q] = 0.f;

    for (int tap = 0; tap < 9; tap++) {
        __syncthreads();
        // stage W (64 rows x 128B)
        for (int i = tid; i < 512; i += 256) {
            int row = i >> 3, q = i & 7;
            int off = row*128 + ((q*16) ^ ((row & 7)*16));
            *(uint4*)(wH + off) = ((const uint4*)&g_wdh[tap*4096])[i];
        }
        // bilinear params (threads 0..127, one pixel each)
        if (tid < 128) {
            const __half* omp = &om16[tid*28];
            float dy = __half2float(omp[tap*2]);
            float dx = __half2float(omp[tap*2+1]);
            float mk = __half2float(omp[18+tap]);
            float py = (float)(h + tap/3 - 1) + dy;
            float px_ = (float)(tid + tap%3 - 1) + dx;
            float fy = floorf(py), fx = floorf(px_);
            float ly = py - fy,    lx = px_ - fx;
            int y0 = (int)fy, x0 = (int)fx;
            int y1 = y0 + 1,  x1 = x0 + 1;
            float vy0 = (y0 >= 0 && y0 < Hn) ? 1.f : 0.f;
            float vy1 = (y1 >= 0 && y1 < Hn) ? 1.f : 0.f;
            float vx0 = (x0 >= 0 && x0 < Wn) ? 1.f : 0.f;
            float vx1 = (x1 >= 0 && x1 < Wn) ? 1.f : 0.f;
            int iy0 = min(max(y0,0),Hn-1), iy1 = min(max(y1,0),Hn-1);
            int ix0 = min(max(x0,0),Wn-1), ix1 = min(max(x1,0),Wn-1);
            int base = (b*Hn)*Wn;
            psm[tid*8+0] = (1.f-ly)*(1.f-lx)*mk * vy0*vx0;
            psm[tid*8+1] = (1.f-ly)*lx      *mk * vy0*vx1;
            psm[tid*8+2] = ly      *(1.f-lx)*mk * vy1*vx0;
            psm[tid*8+3] = ly      *lx      *mk * vy1*vx1;
            psm[tid*8+4] = __int_as_float(base + iy0*Wn + ix0);
            psm[tid*8+5] = __int_as_float(base + iy0*Wn + ix1);
            psm[tid*8+6] = __int_as_float(base + iy1*Wn + ix0);
            psm[tid*8+7] = __int_as_float(base + iy1*Wn + ix1);
        }
        __syncthreads();
        // gather (16B lanes) + HALF2 blend (HFMA2) + store
        #pragma unroll
        for (int it = 0; it < 4; it++) {
            int px = it*32 + grp8;
            __half2 W00 = __float2half2_rn(psm[px*8+0]);
            __half2 W01 = __float2half2_rn(psm[px*8+1]);
            __half2 W10 = __float2half2_rn(psm[px*8+2]);
            __half2 W11 = __float2half2_rn(psm[px*8+3]);
            int i00 = __float_as_int(psm[px*8+4]);
            int i01 = __float_as_int(psm[px*8+5]);
            int i10 = __float_as_int(psm[px*8+6]);
            int i11 = __float_as_int(psm[px*8+7]);
            uint4 ua = *(const uint4*)&g_x16[(size_t)i00*Cn + c8*8];
            uint4 ue = *(const uint4*)&g_x16[(size_t)i01*Cn + c8*8];
            uint4 uc = *(const uint4*)&g_x16[(size_t)i10*Cn + c8*8];
            uint4 ud = *(const uint4*)&g_x16[(size_t)i11*Cn + c8*8];
            uint4 outv;
            const uint32_t* pa = &ua.x;
            const uint32_t* pe = &ue.x;
            const uint32_t* pc = &uc.x;
            const uint32_t* pd = &ud.x;
            uint32_t* po = &outv.x;
            #pragma unroll
            for (int j = 0; j < 4; j++) {
                __half2 av = *(const __half2*)&pa[j];
                __half2 ev = *(const __half2*)&pe[j];
                __half2 cv = *(const __half2*)&pc[j];
                __half2 dv = *(const __half2*)&pd[j];
                __half2 r = __hfma2(av, W00,
                            __hfma2(ev, W01,
                            __hfma2(cv, W10, __hmul2(dv, W11))));
                po[j] = *(const uint32_t*)&r;
            }
            int off = px*128 + ((c8*16) ^ ((px & 7)*16));
            *(uint4*)(aH + off) = outv;
        }
        __syncthreads();
        #pragma unroll
        for (int ks = 0; ks < 4; ks++) {
            uint32_t aoff = aRowOff + ((acol + ks*32) ^ asw);
            uint32_t ah0,ah1,ah2,ah3;
            LDSM4(ah0,ah1,ah2,ah3, aHb + aoff);
            #pragma unroll
            for (int np = 0; np < 4; np++) {
                uint32_t boff = (np*16 + browb)*128 + ((bcol + ks*32) ^ bsw);
                uint32_t bh0,bh1,bh2,bh3;
                LDSM4(bh0,bh1,bh2,bh3, wHb + boff);
                MMA16816(dacc[2*np][0],dacc[2*np][1],dacc[2*np][2],dacc[2*np][3],
                         ah0,ah1,ah2,ah3, bh0,bh1);
                MMA16816(dacc[2*np+1][0],dacc[2*np+1][1],dacc[2*np+1][2],dacc[2*np+1][3],
                         ah0,ah1,ah2,ah3, bh2,bh3);
            }
        }
    }

    // epilogue: +bias, store y (fp16), fused BN stats (fp32)
    __syncthreads();
    if (tid < 128) psm[tid] = 0.f;
    __syncthreads();

    int px = p0 + wid*16 + g;
    float ss[8], sh[8], qs[8], qh[8];
    #pragma unroll
    for (int nt = 0; nt < 8; nt++) {
        int o = nt*8 + 2*tc;
        float b0 = bias[o], b1 = bias[o+1];
        float v00 = dacc[nt][0] + b0, v01 = dacc[nt][1] + b1;
        float v10 = dacc[nt][2] + b0, v11 = dacc[nt][3] + b1;
        __half2 r0 = __floats2half2_rn(v00, v01);
        __half2 r1 = __floats2half2_rn(v10, v11);
        *(__half2*)&g_y16[(size_t)px*64 + o]     = r0;
        *(__half2*)&g_y16[(size_t)(px+8)*64 + o] = r1;
        ss[nt] = v00 + v10;        sh[nt] = v01 + v11;
        qs[nt] = v00*v00 + v10*v10; qh[nt] = v01*v01 + v11*v11;
    }
    #pragma unroll
    for (int d = 4; d < 32; d <<= 1) {
        #pragma unroll
        for (int nt = 0; nt < 8; nt++) {
            ss[nt] += __shfl_xor_sync(0xffffffffu, ss[nt], d);
            sh[nt] += __shfl_xor_sync(0xffffffffu, sh[nt], d);
            qs[nt] += __shfl_xor_sync(0xffffffffu, qs[nt], d);
            qh[nt] += __shfl_xor_sync(0xffffffffu, qh[nt], d);
        }
    }
    if (lane < 4) {
        #pragma unroll
        for (int nt = 0; nt < 8; nt++) {
            int o = nt*8 + 2*tc;
            atomicAdd(&psm[o],       ss[nt]);
            atomicAdd(&psm[o+1],     sh[nt]);
            atomicAdd(&psm[64+o],    qs[nt]);
            atomicAdd(&psm[64+o+1],  qh[nt]);
        }
    }
    __syncthreads();
    if (tid < 64) {
        atomicAdd(&g_sum[tid], psm[tid]);
        atomicAdd(&g_sq [tid], psm[64+tid]);
    }
}

// ---------------------------------------------------------------------------
// Normalize + affine + ReLU, NHWC(fp16) -> NCHW(fp32). 2 channels/thread.
__global__ __launch_bounds__(512) void k_norm_out(
    const float* __restrict__ gamma, const float* __restrict__ beta,
    float* __restrict__ out)
{
    __shared__ float t[32][33];
    int w0 = blockIdx.x * 32, c0 = blockIdx.y * 32;
    int bh = blockIdx.z;
    int b = bh / Hn, h = bh % Hn;
    int tx = threadIdx.x, ty2 = threadIdx.y;   // ty2: 0..15, handles rows 2*ty2, 2*ty2+1 of c-dim? no:
    // layout: tx = w within tile (32), ty2*2 = channel pair within tile
    int c = c0 + 2*ty2;    // this thread handles channels c, c+1 at pixel w0+tx

    const float inv = 1.0f / (float)PIX;
    float m0 = g_sum[c] * inv,   m1 = g_sum[c+1] * inv;
    float v0 = g_sq[c] * inv - m0*m0, v1 = g_sq[c+1] * inv - m1*m1;
    float r0 = rsqrtf(v0 + 1e-5f), r1 = rsqrtf(v1 + 1e-5f);
    float sc0 = gamma[c]*r0,   sc1 = gamma[c+1]*r1;
    float sh0 = beta[c]-m0*sc0, sh1 = beta[c+1]-m1*sc1;

    __half2 yv = *(const __half2*)&g_y16[((size_t)bh*Wn + (w0+tx))*Cn + c];
    float2 yf = __half22float2(yv);
    t[2*ty2][tx]   = fmaxf(yf.x*sc0 + sh0, 0.f);
    t[2*ty2+1][tx] = fmaxf(yf.y*sc1 + sh1, 0.f);
    __syncthreads();
    // write out NCHW: thread (tx, ty2) writes channels tile rows
    #pragma unroll
    for (int j = 0; j < 2; j++) {
        int cc = c0 + 2*ty2 + j;
        out[(((size_t)b*Cn + cc)*Hn + h)*Wn + (w0+tx)] = t[2*ty2+j][tx];
    }
}

// ---------------------------------------------------------------------------
extern "C" void kernel_launch(void* const* d_in, const int* in_sizes, int n_in,
                              void* d_out, int out_size)
{
    const float* x     = (const float*)d_in[0];
    const float* off_w = (const float*)d_in[1];
    const float* off_b = (const float*)d_in[2];
    const float* mod_w = (const float*)d_in[3];
    const float* mod_b = (const float*)d_in[4];
    const float* wmat  = (const float*)d_in[5];
    const float* bias  = (const float*)d_in[6];
    const float* gamma = (const float*)d_in[7];
    const float* beta  = (const float*)d_in[8];
    float* out = (float*)d_out;

    static int configured = 0;
    if (!configured) {
        cudaFuncSetAttribute(k_conv, cudaFuncAttributeMaxDynamicSharedMemorySize, FSM);
        configured = 1;
    }

    dim3 tgrid(Wn/32, Cn/32, Bn*Hn);
    dim3 tblk(32, 32);
    dim3 ngrid(Wn/32, Cn/32, Bn*Hn);
    dim3 nblk(32, 16);

    k_zero<<<1, 64>>>();
    k_wprep<<<64, 256>>>(wmat, off_w, mod_w);
    k_transpose_in<<<tgrid, tblk>>>(x);
    k_conv<<<PIX/128, 256, FSM>>>(off_b, mod_b, bias);
    k_norm_out<<<ngrid, nblk>>>(gamma, beta, out);
}